// round 1
// baseline (speedup 1.0000x reference)
#include <cuda_runtime.h>
#include <math.h>

// Problem constants
#define Bb 4
#define Ss 2048
#define T  8192          // Bb*Ss tokens
#define Hh 512
#define Ff 2048
#define Ee 8
#define Kk 2
#define TK 16384         // T*Kk slots

// ---------------- scratch (static device globals; no allocation allowed) ----
__device__ float g_act[(size_t)TK * Ff];   // post-GELU activations per slot
__device__ float g_y[(size_t)TK * Hh];     // per-slot expert outputs
__device__ float g_topk_p[TK];             // renormalized top-k probs
__device__ int   g_topk_i[TK];             // top-k expert indices
__device__ int   g_counts[Ee];
__device__ int   g_offs[Ee + 1];
__device__ int   g_run[Ee];
__device__ int   g_perm[TK];               // expert-grouped list of slots

// ---------------------------------------------------------------- utilities
__global__ void zero_counts_kernel() {
    int i = threadIdx.x;
    if (i < Ee) g_counts[i] = 0;
}

__global__ void scan_kernel() {
    int a = 0;
    for (int e = 0; e < Ee; ++e) {
        g_offs[e] = a;
        g_run[e]  = a;
        a += g_counts[e];
    }
    g_offs[Ee] = a;
}

__global__ void scatter_kernel() {
    int t = blockIdx.x * 256 + threadIdx.x;
    if (t >= T) return;
#pragma unroll
    for (int k = 0; k < Kk; ++k) {
        int e   = g_topk_i[2 * t + k];
        int pos = atomicAdd(&g_run[e], 1);
        g_perm[pos] = 2 * t + k;
    }
}

// ------------------------------------------------------------------- router
// one warp per token: logits = x . router_w[e], softmax, top-2, renormalize
__global__ void router_kernel(const float* __restrict__ x,
                              const float* __restrict__ rw,
                              float* __restrict__ out_probs,
                              float* __restrict__ out_idx) {
    __shared__ float rws[Ee * Hh];
    int tid = threadIdx.x;
    for (int i = tid; i < Ee * Hh; i += 256) rws[i] = rw[i];
    __syncthreads();

    int warp = tid >> 5, lane = tid & 31;
    int t = blockIdx.x * 8 + warp;
    const float* xr = x + (size_t)t * Hh;

    float xv[16];
#pragma unroll
    for (int j = 0; j < 16; ++j) xv[j] = xr[lane + 32 * j];

    float logit[Ee];
#pragma unroll
    for (int e = 0; e < Ee; ++e) {
        float acc = 0.f;
#pragma unroll
        for (int j = 0; j < 16; ++j) acc += xv[j] * rws[e * Hh + lane + 32 * j];
#pragma unroll
        for (int o = 16; o; o >>= 1) acc += __shfl_xor_sync(0xffffffffu, acc, o);
        logit[e] = acc;
    }

    if (lane == 0) {
        float mx = logit[0];
#pragma unroll
        for (int e = 1; e < Ee; ++e) mx = fmaxf(mx, logit[e]);
        float p[Ee], den = 0.f;
#pragma unroll
        for (int e = 0; e < Ee; ++e) { p[e] = __expf(logit[e] - mx); den += p[e]; }
        // use precise expf to match reference closely
#pragma unroll
        for (int e = 0; e < Ee; ++e) p[e] = expf(logit[e] - mx);
        den = 0.f;
#pragma unroll
        for (int e = 0; e < Ee; ++e) den += p[e];
        float inv = 1.f / den;

        int i0 = 0;
#pragma unroll
        for (int e = 1; e < Ee; ++e) if (p[e] > p[i0]) i0 = e;
        int i1 = (i0 == 0) ? 1 : 0;
#pragma unroll
        for (int e = 0; e < Ee; ++e) if (e != i0 && p[e] > p[i1]) i1 = e;

        float p0 = p[i0] * inv, p1 = p[i1] * inv;
        float rden = 1.f / (p0 + p1 + 1e-9f);

#pragma unroll
        for (int e = 0; e < Ee; ++e) out_probs[(size_t)t * Ee + e] = p[e] * inv;
        out_idx[2 * t + 0] = (float)i0;
        out_idx[2 * t + 1] = (float)i1;
        g_topk_p[2 * t + 0] = p0 * rden;
        g_topk_p[2 * t + 1] = p1 * rden;
        g_topk_i[2 * t + 0] = i0;
        g_topk_i[2 * t + 1] = i1;
        atomicAdd(&g_counts[i0], 1);
        atomicAdd(&g_counts[i1], 1);
    }
}

// ------------------------------------------------------------- expert GEMMs
// NT-layout GEMM with row gathering. BM=BN=128, BK=16, 256 threads, 8x8/thread.
// G1:  C[slot, 0:F] = gelu( x[slot>>1, :] @ fc1_w[e].T + fc1_b[e] )
// !G1: C[slot, 0:H] =       g_act[slot, :] @ fc2_w[e].T + fc2_b[e]
template <int NDIM, int KDIM, bool G1>
__global__ void __launch_bounds__(256, 2)
ffn_gemm(const float* __restrict__ X,
         const float* __restrict__ W,
         const float* __restrict__ bias) {
    const float* Abase = G1 ? X : g_act;
    float*       C     = G1 ? g_act : g_y;
    const int NT = NDIM / 128;

    // locate (expert, m-tile, n-tile) for this block
    int b = blockIdx.x;
    int e = -1, mt = 0, nt = 0, acc = 0;
#pragma unroll
    for (int ee = 0; ee < Ee; ++ee) {
        int cnt = g_offs[ee + 1] - g_offs[ee];
        int mts = (cnt + 127) >> 7;
        int tot = mts * NT;
        if (b < acc + tot) { e = ee; int loc = b - acc; mt = loc / NT; nt = loc % NT; break; }
        acc += tot;
    }
    if (e < 0) return;

    __shared__ float As[16][132];
    __shared__ float Bs[16][132];
    __shared__ int   s_slot[128];

    int tid = threadIdx.x;
    int base = g_offs[e] + mt * 128;
    int end  = g_offs[e + 1];
    if (tid < 128) {
        int r = base + tid;
        s_slot[tid] = (r < end) ? g_perm[r] : -1;
    }
    __syncthreads();

    const float* Wt = W + (size_t)e * NDIM * KDIM + (size_t)(nt * 128) * KDIM;

    int tm = tid >> 4, tn = tid & 15;
    int la_m = tid >> 2;          // 0..63
    int la_k = (tid & 3) * 4;     // 0,4,8,12

    float accv[8][8];
#pragma unroll
    for (int i = 0; i < 8; ++i)
#pragma unroll
        for (int j = 0; j < 8; ++j) accv[i][j] = 0.f;

    for (int k0 = 0; k0 < KDIM; k0 += 16) {
        // load A tile (gathered rows), transposed into As[k][m]
#pragma unroll
        for (int h = 0; h < 2; ++h) {
            int m = la_m + h * 64;
            int slot = s_slot[m];
            float4 v = make_float4(0.f, 0.f, 0.f, 0.f);
            if (slot >= 0) {
                int row = G1 ? (slot >> 1) : slot;
                v = *(const float4*)(Abase + (size_t)row * KDIM + k0 + la_k);
            }
            As[la_k + 0][m] = v.x; As[la_k + 1][m] = v.y;
            As[la_k + 2][m] = v.z; As[la_k + 3][m] = v.w;
        }
        // load B tile (weights, row-major [N][K]) transposed into Bs[k][n]
#pragma unroll
        for (int h = 0; h < 2; ++h) {
            int n = la_m + h * 64;
            float4 v = *(const float4*)(Wt + (size_t)n * KDIM + k0 + la_k);
            Bs[la_k + 0][n] = v.x; Bs[la_k + 1][n] = v.y;
            Bs[la_k + 2][n] = v.z; Bs[la_k + 3][n] = v.w;
        }
        __syncthreads();

#pragma unroll
        for (int kk = 0; kk < 16; ++kk) {
            float4 a0 = *(const float4*)&As[kk][tm * 8];
            float4 a1 = *(const float4*)&As[kk][tm * 8 + 4];
            float4 b0 = *(const float4*)&Bs[kk][tn * 8];
            float4 b1 = *(const float4*)&Bs[kk][tn * 8 + 4];
            float av[8] = {a0.x, a0.y, a0.z, a0.w, a1.x, a1.y, a1.z, a1.w};
            float bv[8] = {b0.x, b0.y, b0.z, b0.w, b1.x, b1.y, b1.z, b1.w};
#pragma unroll
            for (int i = 0; i < 8; ++i)
#pragma unroll
                for (int j = 0; j < 8; ++j) accv[i][j] += av[i] * bv[j];
        }
        __syncthreads();
    }

    // epilogue: + bias (, GELU), scatter rows to slot-indexed C
    float bv[8];
#pragma unroll
    for (int j = 0; j < 8; ++j)
        bv[j] = bias[(size_t)e * NDIM + nt * 128 + tn * 8 + j];

#pragma unroll
    for (int i = 0; i < 8; ++i) {
        int m = tm * 8 + i;
        int slot = s_slot[m];
        if (slot < 0) continue;
        float* crow = C + (size_t)slot * NDIM + nt * 128 + tn * 8;
        float v[8];
#pragma unroll
        for (int j = 0; j < 8; ++j) {
            float z = accv[i][j] + bv[j];
            if (G1) z = 0.5f * z * (1.f + erff(z * 0.70710678118654752f));
            v[j] = z;
        }
        *(float4*)(crow + 0) = make_float4(v[0], v[1], v[2], v[3]);
        *(float4*)(crow + 4) = make_float4(v[4], v[5], v[6], v[7]);
    }
}

// ----------------------------------------------------------------- combine
__global__ void combine_kernel(float* __restrict__ out) {
    int t = blockIdx.x;
    float p0 = g_topk_p[2 * t], p1 = g_topk_p[2 * t + 1];
    const float4* y0 = (const float4*)(g_y + (size_t)(2 * t) * Hh);
    const float4* y1 = (const float4*)(g_y + (size_t)(2 * t + 1) * Hh);
    float4* o = (float4*)(out + (size_t)t * Hh);
    int i = threadIdx.x;  // 128 threads, Hh/4 = 128 float4s
    float4 a = y0[i], b = y1[i];
    o[i] = make_float4(p0 * a.x + p1 * b.x, p0 * a.y + p1 * b.y,
                       p0 * a.z + p1 * b.z, p0 * a.w + p1 * b.w);
}

// ------------------------------------------------------------------- launch
extern "C" void kernel_launch(void* const* d_in, const int* in_sizes, int n_in,
                              void* d_out, int out_size) {
    (void)in_sizes; (void)n_in; (void)out_size;
    const float* x    = (const float*)d_in[0];
    const float* rw   = (const float*)d_in[1];
    const float* fc1w = (const float*)d_in[2];
    const float* fc1b = (const float*)d_in[3];
    const float* fc2w = (const float*)d_in[4];
    const float* fc2b = (const float*)d_in[5];

    float* out       = (float*)d_out;                 // [T, Hh]
    float* out_probs = out + (size_t)T * Hh;          // [T, Ee]
    float* out_idx   = out_probs + (size_t)T * Ee;    // [T, Kk] as float

    zero_counts_kernel<<<1, 32>>>();
    router_kernel<<<T / 8, 256>>>(x, rw, out_probs, out_idx);
    scan_kernel<<<1, 1>>>();
    scatter_kernel<<<T / 256, 256>>>();

    // worst-case tile bound: sum_e ceil(cnt_e/128) <= 128 + 8 = 136
    ffn_gemm<Ff, Hh, true ><<<136 * (Ff / 128), 256>>>(x, fc1w, fc1b);
    ffn_gemm<Hh, Ff, false><<<136 * (Hh / 128), 256>>>(x, fc2w, fc2b);

    combine_kernel<<<T, 128>>>(out);
}

// round 6
// speedup vs baseline: 2.1741x; 2.1741x over previous
#include <cuda_runtime.h>
#include <cuda_bf16.h>
#include <math.h>
#include <stdint.h>

// ---------------------------------------------------------------- constants
#define T   8192         // tokens (B*S)
#define Hh  512
#define Ff  2048
#define Ee  8
#define TK  16384        // T*K slots

// ---------------------------------------------------------------- scratch
// hi/lo split layouts: row = [hi(0..K-1) | lo(K..2K-1)]
__device__ __nv_bfloat16 g_xb [(size_t)T  * 2 * Hh];       // x split
__device__ __nv_bfloat16 g_w1b[(size_t)Ee * Ff * 2 * Hh];  // fc1_w split
__device__ __nv_bfloat16 g_w2b[(size_t)Ee * Hh * 2 * Ff];  // fc2_w split
__device__ __nv_bfloat16 g_act[(size_t)TK * 2 * Ff];       // gelu acts split
__device__ float g_y[(size_t)TK * Hh];
__device__ float g_topk_p[TK];
__device__ int   g_topk_i[TK];
__device__ int   g_counts[Ee];
__device__ int   g_offs[Ee + 1];
__device__ int   g_run[Ee];
__device__ int   g_perm[TK];

// ---------------------------------------------------------------- PTX utils
__device__ __forceinline__ uint32_t smem_u32(const void* p) {
    uint32_t a;
    asm("{ .reg .u64 t; cvta.to.shared.u64 t, %1; cvt.u32.u64 %0, t; }"
        : "=r"(a) : "l"(p));
    return a;
}
__device__ __forceinline__ void cp_async16(uint32_t dst, const void* src, int sz) {
    asm volatile("cp.async.cg.shared.global [%0], [%1], 16, %2;"
                 :: "r"(dst), "l"(src), "r"(sz));
}
#define CP_COMMIT()  asm volatile("cp.async.commit_group;" ::: "memory")
#define CP_WAIT1()   asm volatile("cp.async.wait_group 1;" ::: "memory")

#define LDS32(r, addr) \
    asm volatile("ld.shared.b32 %0,[%1];" : "=r"(r) : "r"(addr))

#define MMA16816(d, a, b0v, b1v) \
    asm volatile("mma.sync.aligned.m16n8k16.row.col.f32.bf16.bf16.f32 " \
                 "{%0,%1,%2,%3},{%4,%5,%6,%7},{%8,%9},{%0,%1,%2,%3};" \
                 : "+f"((d)[0]), "+f"((d)[1]), "+f"((d)[2]), "+f"((d)[3]) \
                 : "r"((a)[0]), "r"((a)[1]), "r"((a)[2]), "r"((a)[3]), \
                   "r"(b0v), "r"(b1v))

// ---------------------------------------------------------------- bookkeeping
__global__ void zero_counts_kernel() {
    int i = threadIdx.x;
    if (i < Ee) g_counts[i] = 0;
}
__global__ void scan_kernel() {
    int a = 0;
    for (int e = 0; e < Ee; ++e) { g_offs[e] = a; g_run[e] = a; a += g_counts[e]; }
    g_offs[Ee] = a;
}
__global__ void scatter_kernel() {
    int t = blockIdx.x * 256 + threadIdx.x;
    if (t >= T) return;
#pragma unroll
    for (int k = 0; k < 2; ++k) {
        int e = g_topk_i[2 * t + k];
        int pos = atomicAdd(&g_run[e], 1);
        g_perm[pos] = 2 * t + k;
    }
}

// ---------------------------------------------------------------- conversion
// fp32 [rows][K] -> bf16 [rows][2K] with hi in [0,K), lo in [K,2K).
// IMPORTANT: destination is a __device__ global selected IN DEVICE CODE.
// (Passing the global's symbol from host gives the host shadow address —
// on GB300 ATS those writes silently land in host memory. Root cause of
// rounds 3-5 bias-only outputs.)
__global__ void conv_split(const float* __restrict__ src,
                           int which, int K, int n4) {
    __nv_bfloat16* dst = (which == 0) ? g_xb : (which == 1) ? g_w1b : g_w2b;
    int q = blockIdx.x * 256 + threadIdx.x;
    if (q >= n4) return;
    int K4 = K >> 2;
    int row = q / K4, c = q - row * K4;
    float4 v = ((const float4*)src)[q];
    __nv_bfloat16 h0 = __float2bfloat16_rn(v.x);
    __nv_bfloat16 h1 = __float2bfloat16_rn(v.y);
    __nv_bfloat16 h2 = __float2bfloat16_rn(v.z);
    __nv_bfloat16 h3 = __float2bfloat16_rn(v.w);
    __nv_bfloat16 l0 = __float2bfloat16_rn(v.x - __bfloat162float(h0));
    __nv_bfloat16 l1 = __float2bfloat16_rn(v.y - __bfloat162float(h1));
    __nv_bfloat16 l2 = __float2bfloat16_rn(v.z - __bfloat162float(h2));
    __nv_bfloat16 l3 = __float2bfloat16_rn(v.w - __bfloat162float(h3));
    __nv_bfloat16 hp[4] = {h0, h1, h2, h3};
    __nv_bfloat16 lp[4] = {l0, l1, l2, l3};
    __nv_bfloat16* base = dst + (size_t)row * 2 * K + c * 4;
    *(uint2*)base       = *(uint2*)hp;
    *(uint2*)(base + K) = *(uint2*)lp;
}

// ---------------------------------------------------------------- router
__global__ void router_kernel(const float* __restrict__ x,
                              const float* __restrict__ rw,
                              float* __restrict__ out_probs,
                              float* __restrict__ out_idx) {
    __shared__ float rws[Ee * Hh];
    int tid = threadIdx.x;
    for (int i = tid; i < Ee * Hh; i += 256) rws[i] = rw[i];
    __syncthreads();

    int warp = tid >> 5, lane = tid & 31;
    int t = blockIdx.x * 8 + warp;
    const float* xr = x + (size_t)t * Hh;

    float xv[16];
#pragma unroll
    for (int j = 0; j < 16; ++j) xv[j] = xr[lane + 32 * j];

    float logit[Ee];
#pragma unroll
    for (int e = 0; e < Ee; ++e) {
        float acc = 0.f;
#pragma unroll
        for (int j = 0; j < 16; ++j) acc += xv[j] * rws[e * Hh + lane + 32 * j];
#pragma unroll
        for (int o = 16; o; o >>= 1) acc += __shfl_xor_sync(0xffffffffu, acc, o);
        logit[e] = acc;
    }

    if (lane == 0) {
        float mx = logit[0];
#pragma unroll
        for (int e = 1; e < Ee; ++e) mx = fmaxf(mx, logit[e]);
        float p[Ee], den = 0.f;
#pragma unroll
        for (int e = 0; e < Ee; ++e) { p[e] = expf(logit[e] - mx); den += p[e]; }
        float inv = 1.f / den;

        int i0 = 0;
#pragma unroll
        for (int e = 1; e < Ee; ++e) if (p[e] > p[i0]) i0 = e;
        int i1 = (i0 == 0) ? 1 : 0;
#pragma unroll
        for (int e = 0; e < Ee; ++e) if (e != i0 && p[e] > p[i1]) i1 = e;

        float p0 = p[i0] * inv, p1 = p[i1] * inv;
        float rden = 1.f / (p0 + p1 + 1e-9f);

#pragma unroll
        for (int e = 0; e < Ee; ++e) out_probs[(size_t)t * Ee + e] = p[e] * inv;
        out_idx[2 * t + 0] = (float)i0;
        out_idx[2 * t + 1] = (float)i1;
        g_topk_p[2 * t + 0] = p0 * rden;
        g_topk_p[2 * t + 1] = p1 * rden;
        g_topk_i[2 * t + 0] = i0;
        g_topk_i[2 * t + 1] = i1;
        atomicAdd(&g_counts[i0], 1);
        atomicAdd(&g_counts[i1], 1);
    }
}

// ---------------------------------------------------------------- HMMA GEMM
// BM=128, BN=128, BK=32 source-K per stage; hi/lo tiles separate; three
// mma passes per k16 (AhBh + AlBh + AhBl). 3-stage cp.async pipeline.
// Fragments via explicit LDS.32 per the PTX mma fragment tables:
//   A (row-major 16x16): lane l -> rows l/4, l/4+8; k 2*(l%4), +8
//   B (col-major 16x8) : lane l -> col l/4; k 2*(l%4) pairs, +8
// SMEM stage: Ah[128][40] Al Bh Bl (stride 40 bf16 = 80B).
static constexpr int STAGE_B  = 4 * 128 * 40 * 2;   // 40960 bytes
static constexpr int SMEM_TOT = 3 * STAGE_B + 512;  // + slot array

template <int KSRC, int NDIM, bool G1>
__global__ void __launch_bounds__(256, 1)
moe_gemm_mma(const float* __restrict__ bias_all) {
    constexpr int NT  = NDIM / 128;
    constexpr int NKB = KSRC / 32;

    // block -> (expert, m-tile, n-tile); n-tile fastest for L2 A reuse
    int b = blockIdx.x;
    int e = -1, mt = 0, nt = 0, acc0 = 0;
    for (int ee = 0; ee < Ee; ++ee) {
        int cnt = g_offs[ee + 1] - g_offs[ee];
        int mts = (cnt + 127) >> 7;
        int tot = mts * NT;
        if (b < acc0 + tot) { e = ee; int loc = b - acc0; mt = loc / NT; nt = loc % NT; break; }
        acc0 += tot;
    }
    if (e < 0) return;

    extern __shared__ char smem[];
    uint32_t smb = smem_u32(smem);
    int* s_slot = (int*)(smem + 3 * STAGE_B);
    int tid = threadIdx.x, wid = tid >> 5, lane = tid & 31;

    {
        int base = g_offs[e] + mt * 128, end = g_offs[e + 1];
        if (tid < 128) {
            int r = base + tid;
            s_slot[tid] = (r < end) ? g_perm[r] : -1;
        }
    }
    __syncthreads();

    const __nv_bfloat16* Wb =
        (G1 ? g_w1b : g_w2b) + ((size_t)e * NDIM + (size_t)nt * 128) * (2 * KSRC);

    auto issue_stage = [&](int kb, int stg) {
        int k0 = kb * 32;
        uint32_t sb = smb + stg * STAGE_B;
#pragma unroll
        for (int i = 0; i < 8; ++i) {
            int q = i * 256 + tid;
            int tile = q >> 9;              // 0=Ah 1=Al 2=Bh 3=Bl
            int rem = q & 511;
            int r = rem >> 2, c = rem & 3;
            uint32_t dst = sb + tile * 10240 + r * 80 + c * 16;
            const __nv_bfloat16* src = g_xb;
            int sz = 16;
            if (tile < 2) {
                int slot = s_slot[r];
                if (slot < 0) sz = 0;
                else {
                    const __nv_bfloat16* rowp =
                        G1 ? (g_xb + (size_t)(slot >> 1) * (2 * KSRC))
                           : (g_act + (size_t)slot * (2 * KSRC));
                    src = rowp + (tile ? KSRC : 0) + k0 + c * 8;
                }
            } else {
                src = Wb + (size_t)r * (2 * KSRC) + ((tile == 3) ? KSRC : 0) + k0 + c * 8;
            }
            cp_async16(dst, src, sz);
        }
        CP_COMMIT();
    };

    int warp_m = wid >> 2, warp_n = wid & 3;
    int g = lane >> 2, cpair = lane & 3;
    float accv[4][4][4];
#pragma unroll
    for (int mi = 0; mi < 4; ++mi)
#pragma unroll
        for (int ni = 0; ni < 4; ++ni)
#pragma unroll
            for (int j = 0; j < 4; ++j) accv[mi][ni][j] = 0.f;

    issue_stage(0, 0);
    issue_stage(1, 1);

    for (int kb = 0; kb < NKB; ++kb) {
        CP_WAIT1();
        __syncthreads();
        uint32_t sb = smb + (kb % 3) * STAGE_B;
#pragma unroll
        for (int kk = 0; kk < 2; ++kk) {
            uint32_t ah[4][4], al[4][4], bh[4][2], bl[4][2];
            // A fragments: (row = warp_m*64 + g (+8, +mi*16), k = kk*16 + 2*cpair (+8))
            uint32_t abase = sb + (uint32_t)(warp_m * 64 + g) * 80 + kk * 32 + cpair * 4;
#pragma unroll
            for (int mi = 0; mi < 4; ++mi) {
                uint32_t a0 = abase + mi * (16 * 80);
                LDS32(ah[mi][0], a0);               // row g      , k 2c
                LDS32(ah[mi][1], a0 + 640);         // row g+8    , k 2c
                LDS32(ah[mi][2], a0 + 16);          // row g      , k 2c+8
                LDS32(ah[mi][3], a0 + 656);         // row g+8    , k 2c+8
                LDS32(al[mi][0], a0 + 10240);
                LDS32(al[mi][1], a0 + 10240 + 640);
                LDS32(al[mi][2], a0 + 10240 + 16);
                LDS32(al[mi][3], a0 + 10240 + 656);
            }
            // B fragments: (col n = warp_n*32 + g (+ni*8), k = kk*16 + 2*cpair (+8))
            uint32_t bbase = sb + 20480 + (uint32_t)(warp_n * 32 + g) * 80 + kk * 32 + cpair * 4;
#pragma unroll
            for (int ni = 0; ni < 4; ++ni) {
                uint32_t b0 = bbase + ni * (8 * 80);
                LDS32(bh[ni][0], b0);               // k 2c
                LDS32(bh[ni][1], b0 + 16);          // k 2c+8
                LDS32(bl[ni][0], b0 + 10240);
                LDS32(bl[ni][1], b0 + 10240 + 16);
            }
#pragma unroll
            for (int mi = 0; mi < 4; ++mi)
#pragma unroll
                for (int ni = 0; ni < 4; ++ni) {
                    MMA16816(accv[mi][ni], ah[mi], bh[ni][0], bh[ni][1]);
                    MMA16816(accv[mi][ni], al[mi], bh[ni][0], bh[ni][1]);
                    MMA16816(accv[mi][ni], ah[mi], bl[ni][0], bl[ni][1]);
                }
        }
        if (kb + 2 < NKB) issue_stage(kb + 2, (kb + 2) % 3);
        else CP_COMMIT();
    }

    // ------------------------------------------------------------ epilogue
    int colb = nt * 128 + warp_n * 32 + 2 * (lane & 3);
#pragma unroll
    for (int mi = 0; mi < 4; ++mi) {
#pragma unroll
        for (int h = 0; h < 2; ++h) {
            int row = warp_m * 64 + mi * 16 + (lane >> 2) + h * 8;
            int slot = s_slot[row];
            if (slot < 0) continue;
            if (G1) {
                __nv_bfloat16* rowp = g_act + (size_t)slot * (2 * Ff);
#pragma unroll
                for (int ni = 0; ni < 4; ++ni) {
                    int n = colb + ni * 8;
                    float v0 = accv[mi][ni][2 * h + 0] + bias_all[(size_t)e * NDIM + n];
                    float v1 = accv[mi][ni][2 * h + 1] + bias_all[(size_t)e * NDIM + n + 1];
                    v0 = 0.5f * v0 * (1.f + erff(v0 * 0.70710678118654752f));
                    v1 = 0.5f * v1 * (1.f + erff(v1 * 0.70710678118654752f));
                    __nv_bfloat16 h0 = __float2bfloat16_rn(v0);
                    __nv_bfloat16 h1 = __float2bfloat16_rn(v1);
                    __nv_bfloat16 l0 = __float2bfloat16_rn(v0 - __bfloat162float(h0));
                    __nv_bfloat16 l1 = __float2bfloat16_rn(v1 - __bfloat162float(h1));
                    __nv_bfloat16 hp[2] = {h0, h1};
                    __nv_bfloat16 lp[2] = {l0, l1};
                    *(uint32_t*)(rowp + n)      = *(uint32_t*)hp;
                    *(uint32_t*)(rowp + Ff + n) = *(uint32_t*)lp;
                }
            } else {
                float* rowp = g_y + (size_t)slot * Hh;
#pragma unroll
                for (int ni = 0; ni < 4; ++ni) {
                    int n = colb + ni * 8;
                    float2 v;
                    v.x = accv[mi][ni][2 * h + 0] + bias_all[(size_t)e * NDIM + n];
                    v.y = accv[mi][ni][2 * h + 1] + bias_all[(size_t)e * NDIM + n + 1];
                    *(float2*)(rowp + n) = v;
                }
            }
        }
    }
}

// ---------------------------------------------------------------- combine
__global__ void combine_kernel(float* __restrict__ out) {
    int t = blockIdx.x;
    float p0 = g_topk_p[2 * t], p1 = g_topk_p[2 * t + 1];
    const float4* y0 = (const float4*)(g_y + (size_t)(2 * t) * Hh);
    const float4* y1 = (const float4*)(g_y + (size_t)(2 * t + 1) * Hh);
    float4* o = (float4*)(out + (size_t)t * Hh);
    int i = threadIdx.x;
    float4 a = y0[i], b = y1[i];
    o[i] = make_float4(p0 * a.x + p1 * b.x, p0 * a.y + p1 * b.y,
                       p0 * a.z + p1 * b.z, p0 * a.w + p1 * b.w);
}

// ---------------------------------------------------------------- launch
extern "C" void kernel_launch(void* const* d_in, const int* in_sizes, int n_in,
                              void* d_out, int out_size) {
    (void)in_sizes; (void)n_in; (void)out_size;
    const float* x    = (const float*)d_in[0];
    const float* rw   = (const float*)d_in[1];
    const float* fc1w = (const float*)d_in[2];
    const float* fc1b = (const float*)d_in[3];
    const float* fc2w = (const float*)d_in[4];
    const float* fc2b = (const float*)d_in[5];

    float* out       = (float*)d_out;                 // [T, Hh]
    float* out_probs = out + (size_t)T * Hh;          // [T, Ee]
    float* out_idx   = out_probs + (size_t)T * Ee;    // [T, 2] as float

    cudaFuncSetAttribute(moe_gemm_mma<Hh, Ff, true>,
                         cudaFuncAttributeMaxDynamicSharedMemorySize, SMEM_TOT);
    cudaFuncSetAttribute(moe_gemm_mma<Ff, Hh, false>,
                         cudaFuncAttributeMaxDynamicSharedMemorySize, SMEM_TOT);

    // hi/lo split conversions (destination selected in device code!)
    conv_split<<<(T * Hh / 4 + 255) / 256, 256>>>(x, 0, Hh, T * Hh / 4);
    conv_split<<<(Ee * Ff * Hh / 4 + 255) / 256, 256>>>(fc1w, 1, Hh, Ee * Ff * Hh / 4);
    conv_split<<<(Ee * Hh * Ff / 4 + 255) / 256, 256>>>(fc2w, 2, Ff, Ee * Hh * Ff / 4);

    zero_counts_kernel<<<1, 32>>>();
    router_kernel<<<T / 8, 256>>>(x, rw, out_probs, out_idx);
    scan_kernel<<<1, 1>>>();
    scatter_kernel<<<T / 256, 256>>>();

    // worst-case m-tiles: sum_e ceil(cnt_e/128) <= 128 + 8 = 136
    moe_gemm_mma<Hh, Ff, true ><<<136 * (Ff / 128), 256, SMEM_TOT>>>(fc1b);
    moe_gemm_mma<Ff, Hh, false><<<136 * (Hh / 128), 256, SMEM_TOT>>>(fc2b);

    combine_kernel<<<T, 128>>>(out);
}

// round 8
// speedup vs baseline: 3.3205x; 1.5273x over previous
#include <cuda_runtime.h>
#include <cuda_bf16.h>
#include <math.h>
#include <stdint.h>

// ---------------------------------------------------------------- constants
#define T   8192         // tokens (B*S)
#define Hh  512
#define Ff  2048
#define Ee  8
#define TK  16384        // T*K slots

// ---------------------------------------------------------------- scratch
// hi/lo split layouts: row = [hi(0..K-1) | lo(K..2K-1)]
__device__ __nv_bfloat16 g_xb [(size_t)T  * 2 * Hh];       // x split
__device__ __nv_bfloat16 g_w1b[(size_t)Ee * Ff * 2 * Hh];  // fc1_w split
__device__ __nv_bfloat16 g_w2b[(size_t)Ee * Hh * 2 * Ff];  // fc2_w split
__device__ __nv_bfloat16 g_act[(size_t)TK * 2 * Ff];       // gelu acts split
__device__ float g_y[(size_t)TK * Hh];
__device__ float g_topk_p[TK];
__device__ int   g_topk_i[TK];
__device__ int   g_counts[Ee];
__device__ int   g_offs[Ee + 1];
__device__ int   g_run[Ee];
__device__ int   g_perm[TK];

// ---------------------------------------------------------------- PTX utils
__device__ __forceinline__ uint32_t smem_u32(const void* p) {
    uint32_t a;
    asm("{ .reg .u64 t; cvta.to.shared.u64 t, %1; cvt.u32.u64 %0, t; }"
        : "=r"(a) : "l"(p));
    return a;
}
__device__ __forceinline__ void cp_async16(uint32_t dst, const void* src, int sz) {
    asm volatile("cp.async.cg.shared.global [%0], [%1], 16, %2;"
                 :: "r"(dst), "l"(src), "r"(sz));
}
#define CP_COMMIT()  asm volatile("cp.async.commit_group;" ::: "memory")
#define CP_WAIT1()   asm volatile("cp.async.wait_group 1;" ::: "memory")

#define LDSM4(r0, r1, r2, r3, addr) \
    asm volatile("ldmatrix.sync.aligned.m8n8.x4.shared.b16 {%0,%1,%2,%3},[%4];" \
                 : "=r"(r0), "=r"(r1), "=r"(r2), "=r"(r3) : "r"(addr))

#define MMA16816(d, a, b0v, b1v) \
    asm volatile("mma.sync.aligned.m16n8k16.row.col.f32.bf16.bf16.f32 " \
                 "{%0,%1,%2,%3},{%4,%5,%6,%7},{%8,%9},{%0,%1,%2,%3};" \
                 : "+f"((d)[0]), "+f"((d)[1]), "+f"((d)[2]), "+f"((d)[3]) \
                 : "r"((a)[0]), "r"((a)[1]), "r"((a)[2]), "r"((a)[3]), \
                   "r"(b0v), "r"(b1v))

// ---------------------------------------------------------------- bookkeeping
__global__ void zero_counts_kernel() {
    int i = threadIdx.x;
    if (i < Ee) g_counts[i] = 0;
}
__global__ void scan_kernel() {
    int a = 0;
    for (int e = 0; e < Ee; ++e) { g_offs[e] = a; g_run[e] = a; a += g_counts[e]; }
    g_offs[Ee] = a;
}
__global__ void scatter_kernel() {
    int t = blockIdx.x * 256 + threadIdx.x;
    if (t >= T) return;
#pragma unroll
    for (int k = 0; k < 2; ++k) {
        int e = g_topk_i[2 * t + k];
        int pos = atomicAdd(&g_run[e], 1);
        g_perm[pos] = 2 * t + k;
    }
}

// ---------------------------------------------------------------- conversion
// fp32 [rows][K] -> bf16 [rows][2K], hi in [0,K), lo in [K,2K).
// Destination __device__ global selected IN DEVICE CODE (host-side symbol
// use gives the host shadow address under GB300 ATS — rounds 3-5 bug).
__global__ void conv_split(const float* __restrict__ src,
                           int which, int K, int n4) {
    __nv_bfloat16* dst = (which == 0) ? g_xb : (which == 1) ? g_w1b : g_w2b;
    int q = blockIdx.x * 256 + threadIdx.x;
    if (q >= n4) return;
    int K4 = K >> 2;
    int row = q / K4, c = q - row * K4;
    float4 v = ((const float4*)src)[q];
    __nv_bfloat16 h0 = __float2bfloat16_rn(v.x);
    __nv_bfloat16 h1 = __float2bfloat16_rn(v.y);
    __nv_bfloat16 h2 = __float2bfloat16_rn(v.z);
    __nv_bfloat16 h3 = __float2bfloat16_rn(v.w);
    __nv_bfloat16 l0 = __float2bfloat16_rn(v.x - __bfloat162float(h0));
    __nv_bfloat16 l1 = __float2bfloat16_rn(v.y - __bfloat162float(h1));
    __nv_bfloat16 l2 = __float2bfloat16_rn(v.z - __bfloat162float(h2));
    __nv_bfloat16 l3 = __float2bfloat16_rn(v.w - __bfloat162float(h3));
    __nv_bfloat16 hp[4] = {h0, h1, h2, h3};
    __nv_bfloat16 lp[4] = {l0, l1, l2, l3};
    __nv_bfloat16* base = dst + (size_t)row * 2 * K + c * 4;
    *(uint2*)base       = *(uint2*)hp;
    *(uint2*)(base + K) = *(uint2*)lp;
}

// ---------------------------------------------------------------- router
__global__ void router_kernel(const float* __restrict__ x,
                              const float* __restrict__ rw,
                              float* __restrict__ out_probs,
                              float* __restrict__ out_idx) {
    __shared__ float rws[Ee * Hh];
    int tid = threadIdx.x;
    for (int i = tid; i < Ee * Hh; i += 256) rws[i] = rw[i];
    __syncthreads();

    int warp = tid >> 5, lane = tid & 31;
    int t = blockIdx.x * 8 + warp;
    const float* xr = x + (size_t)t * Hh;

    float xv[16];
#pragma unroll
    for (int j = 0; j < 16; ++j) xv[j] = xr[lane + 32 * j];

    float logit[Ee];
#pragma unroll
    for (int e = 0; e < Ee; ++e) {
        float acc = 0.f;
#pragma unroll
        for (int j = 0; j < 16; ++j) acc += xv[j] * rws[e * Hh + lane + 32 * j];
#pragma unroll
        for (int o = 16; o; o >>= 1) acc += __shfl_xor_sync(0xffffffffu, acc, o);
        logit[e] = acc;
    }

    if (lane == 0) {
        float mx = logit[0];
#pragma unroll
        for (int e = 1; e < Ee; ++e) mx = fmaxf(mx, logit[e]);
        float p[Ee], den = 0.f;
#pragma unroll
        for (int e = 0; e < Ee; ++e) { p[e] = expf(logit[e] - mx); den += p[e]; }
        float inv = 1.f / den;

        int i0 = 0;
#pragma unroll
        for (int e = 1; e < Ee; ++e) if (p[e] > p[i0]) i0 = e;
        int i1 = (i0 == 0) ? 1 : 0;
#pragma unroll
        for (int e = 0; e < Ee; ++e) if (e != i0 && p[e] > p[i1]) i1 = e;

        float p0 = p[i0] * inv, p1 = p[i1] * inv;
        float rden = 1.f / (p0 + p1 + 1e-9f);

#pragma unroll
        for (int e = 0; e < Ee; ++e) out_probs[(size_t)t * Ee + e] = p[e] * inv;
        out_idx[2 * t + 0] = (float)i0;
        out_idx[2 * t + 1] = (float)i1;
        g_topk_p[2 * t + 0] = p0 * rden;
        g_topk_p[2 * t + 1] = p1 * rden;
        g_topk_i[2 * t + 0] = i0;
        g_topk_i[2 * t + 1] = i1;
        atomicAdd(&g_counts[i0], 1);
        atomicAdd(&g_counts[i1], 1);
    }
}

// ---------------------------------------------------------------- HMMA GEMM
// CTA tile 128x256, warp tile 64x64 (warp grid 2x4), BK=32 source-K/stage.
// hi/lo split, 3 mma terms per k16 (AhBh + AlBh + AhBl).
// 3-stage cp.async pipeline; fragments via ldmatrix.x4 (no .trans; layout
// verified against the round-6 LDS32 fragment tables).
// Stage layout (80B row stride, conflict-free): Ah[128] Al[128] Bh[256] Bl[256].
static constexpr int STAGE_B  = (2 * 128 + 2 * 256) * 80;   // 61440 bytes
static constexpr int SMEM_TOT = 3 * STAGE_B + 512;          // + slot array

template <int KSRC, int NDIM, bool G1>
__global__ void __launch_bounds__(256, 1)
moe_gemm_mma(const float* __restrict__ bias_all) {
    constexpr int NT  = NDIM / 256;
    constexpr int NKB = KSRC / 32;

    // block -> (expert, m-tile, n-tile)
    int b = blockIdx.x;
    int e = -1, mt = 0, nt = 0, acc0 = 0;
    for (int ee = 0; ee < Ee; ++ee) {
        int cnt = g_offs[ee + 1] - g_offs[ee];
        int mts = (cnt + 127) >> 7;
        int tot = mts * NT;
        if (b < acc0 + tot) { e = ee; int loc = b - acc0; mt = loc / NT; nt = loc % NT; break; }
        acc0 += tot;
    }
    if (e < 0) return;

    extern __shared__ char smem[];
    uint32_t smb = smem_u32(smem);
    int* s_slot = (int*)(smem + 3 * STAGE_B);
    int tid = threadIdx.x, wid = tid >> 5, lane = tid & 31;

    {
        int base = g_offs[e] + mt * 128, end = g_offs[e + 1];
        if (tid < 128) {
            int r = base + tid;
            s_slot[tid] = (r < end) ? g_perm[r] : -1;
        }
    }
    __syncthreads();

    const __nv_bfloat16* Wb =
        (G1 ? g_w1b : g_w2b) + ((size_t)e * NDIM + (size_t)nt * 256) * (2 * KSRC);

    // stage loader: 3072 16B chunks -> 12 per thread
    auto issue_stage = [&](int kb, int stg) {
        int k0 = kb * 32;
        uint32_t sb = smb + stg * STAGE_B;
#pragma unroll
        for (int i = 0; i < 12; ++i) {
            int q = i * 256 + tid;
            if (q < 1024) {                       // A tiles (hi, lo)
                int half = q >> 9;
                int rem = q & 511;
                int r = rem >> 2, c = rem & 3;
                uint32_t dst = sb + half * 10240 + r * 80 + c * 16;
                int slot = s_slot[r];
                if (slot >= 0) {
                    const __nv_bfloat16* rowp =
                        G1 ? (g_xb + (size_t)(slot >> 1) * (2 * KSRC))
                           : (g_act + (size_t)slot * (2 * KSRC));
                    cp_async16(dst, rowp + half * KSRC + k0 + c * 8, 16);
                } else {
                    cp_async16(dst, g_xb, 0);     // zero-fill
                }
            } else {                              // B tiles (hi, lo)
                int idx = q - 1024;
                int half = idx >> 10;
                int rem = idx & 1023;
                int r = rem >> 2, c = rem & 3;
                uint32_t dst = sb + 20480 + half * 20480 + r * 80 + c * 16;
                cp_async16(dst, Wb + (size_t)r * (2 * KSRC) + half * KSRC + k0 + c * 8, 16);
            }
        }
        CP_COMMIT();
    };

    int warp_m = wid >> 2, warp_n = wid & 3;
    float accv[4][8][4];
#pragma unroll
    for (int mi = 0; mi < 4; ++mi)
#pragma unroll
        for (int ni = 0; ni < 8; ++ni)
#pragma unroll
            for (int j = 0; j < 4; ++j) accv[mi][ni][j] = 0.f;

    // ldmatrix lane address components: row = base + (lane&15), +16B if lane>=16
    uint32_t lmrow = lane & 15;
    uint32_t lkc16 = (lane >> 4) * 16;

    issue_stage(0, 0);
    issue_stage(1, 1);

    for (int kb = 0; kb < NKB; ++kb) {
        CP_WAIT1();
        __syncthreads();
        uint32_t sb = smb + (kb % 3) * STAGE_B;
#pragma unroll
        for (int kk = 0; kk < 2; ++kk) {
            uint32_t ah[4][4], al[4][4], bh[8][2], bl[8][2];
            uint32_t aaddr = sb + (warp_m * 64 + lmrow) * 80 + kk * 32 + lkc16;
            uint32_t baddr = sb + 20480 + (warp_n * 64 + lmrow) * 80 + kk * 32 + lkc16;
#pragma unroll
            for (int mi = 0; mi < 4; ++mi) {
                LDSM4(ah[mi][0], ah[mi][1], ah[mi][2], ah[mi][3], aaddr + mi * 1280);
                LDSM4(al[mi][0], al[mi][1], al[mi][2], al[mi][3], aaddr + 10240 + mi * 1280);
            }
#pragma unroll
            for (int p = 0; p < 4; ++p)
                LDSM4(bh[2 * p][0], bh[2 * p + 1][0], bh[2 * p][1], bh[2 * p + 1][1],
                      baddr + p * 1280);
#pragma unroll
            for (int mi = 0; mi < 4; ++mi)
#pragma unroll
                for (int ni = 0; ni < 8; ++ni) {
                    MMA16816(accv[mi][ni], ah[mi], bh[ni][0], bh[ni][1]);
                    MMA16816(accv[mi][ni], al[mi], bh[ni][0], bh[ni][1]);
                }
#pragma unroll
            for (int p = 0; p < 4; ++p)
                LDSM4(bl[2 * p][0], bl[2 * p + 1][0], bl[2 * p][1], bl[2 * p + 1][1],
                      baddr + 20480 + p * 1280);
#pragma unroll
            for (int mi = 0; mi < 4; ++mi)
#pragma unroll
                for (int ni = 0; ni < 8; ++ni)
                    MMA16816(accv[mi][ni], ah[mi], bl[ni][0], bl[ni][1]);
        }
        if (kb + 2 < NKB) issue_stage(kb + 2, (kb + 2) % 3);
        else CP_COMMIT();
    }

    // ------------------------------------------------------------ epilogue
    int colb = nt * 256 + warp_n * 64 + 2 * (lane & 3);
    float2 bb[8];
#pragma unroll
    for (int ni = 0; ni < 8; ++ni) {
        bb[ni].x = bias_all[(size_t)e * NDIM + colb + ni * 8];
        bb[ni].y = bias_all[(size_t)e * NDIM + colb + ni * 8 + 1];
    }
#pragma unroll
    for (int mi = 0; mi < 4; ++mi) {
#pragma unroll
        for (int h = 0; h < 2; ++h) {
            int row = warp_m * 64 + mi * 16 + (lane >> 2) + h * 8;
            int slot = s_slot[row];
            if (slot < 0) continue;
            if (G1) {
                __nv_bfloat16* rowp = g_act + (size_t)slot * (2 * Ff);
#pragma unroll
                for (int ni = 0; ni < 8; ++ni) {
                    int n = colb + ni * 8;
                    float v0 = accv[mi][ni][2 * h + 0] + bb[ni].x;
                    float v1 = accv[mi][ni][2 * h + 1] + bb[ni].y;
                    v0 = 0.5f * v0 * (1.f + erff(v0 * 0.70710678118654752f));
                    v1 = 0.5f * v1 * (1.f + erff(v1 * 0.70710678118654752f));
                    __nv_bfloat16 h0 = __float2bfloat16_rn(v0);
                    __nv_bfloat16 h1 = __float2bfloat16_rn(v1);
                    __nv_bfloat16 l0 = __float2bfloat16_rn(v0 - __bfloat162float(h0));
                    __nv_bfloat16 l1 = __float2bfloat16_rn(v1 - __bfloat162float(h1));
                    __nv_bfloat16 hp[2] = {h0, h1};
                    __nv_bfloat16 lp[2] = {l0, l1};
                    *(uint32_t*)(rowp + n)      = *(uint32_t*)hp;
                    *(uint32_t*)(rowp + Ff + n) = *(uint32_t*)lp;
                }
            } else {
                float* rowp = g_y + (size_t)slot * Hh;
#pragma unroll
                for (int ni = 0; ni < 8; ++ni) {
                    int n = colb + ni * 8;
                    float2 v;
                    v.x = accv[mi][ni][2 * h + 0] + bb[ni].x;
                    v.y = accv[mi][ni][2 * h + 1] + bb[ni].y;
                    *(float2*)(rowp + n) = v;
                }
            }
        }
    }
}

// ---------------------------------------------------------------- combine
__global__ void combine_kernel(float* __restrict__ out) {
    int t = blockIdx.x;
    float p0 = g_topk_p[2 * t], p1 = g_topk_p[2 * t + 1];
    const float4* y0 = (const float4*)(g_y + (size_t)(2 * t) * Hh);
    const float4* y1 = (const float4*)(g_y + (size_t)(2 * t + 1) * Hh);
    float4* o = (float4*)(out + (size_t)t * Hh);
    int i = threadIdx.x;
    float4 a = y0[i], b = y1[i];
    o[i] = make_float4(p0 * a.x + p1 * b.x, p0 * a.y + p1 * b.y,
                       p0 * a.z + p1 * b.z, p0 * a.w + p1 * b.w);
}

// ---------------------------------------------------------------- launch
extern "C" void kernel_launch(void* const* d_in, const int* in_sizes, int n_in,
                              void* d_out, int out_size) {
    (void)in_sizes; (void)n_in; (void)out_size;
    const float* x    = (const float*)d_in[0];
    const float* rw   = (const float*)d_in[1];
    const float* fc1w = (const float*)d_in[2];
    const float* fc1b = (const float*)d_in[3];
    const float* fc2w = (const float*)d_in[4];
    const float* fc2b = (const float*)d_in[5];

    float* out       = (float*)d_out;                 // [T, Hh]
    float* out_probs = out + (size_t)T * Hh;          // [T, Ee]
    float* out_idx   = out_probs + (size_t)T * Ee;    // [T, 2] as float

    cudaFuncSetAttribute(moe_gemm_mma<Hh, Ff, true>,
                         cudaFuncAttributeMaxDynamicSharedMemorySize, SMEM_TOT);
    cudaFuncSetAttribute(moe_gemm_mma<Ff, Hh, false>,
                         cudaFuncAttributeMaxDynamicSharedMemorySize, SMEM_TOT);

    // hi/lo split conversions (destination selected in device code!)
    conv_split<<<(T * Hh / 4 + 255) / 256, 256>>>(x, 0, Hh, T * Hh / 4);
    conv_split<<<(Ee * Ff * Hh / 4 + 255) / 256, 256>>>(fc1w, 1, Hh, Ee * Ff * Hh / 4);
    conv_split<<<(Ee * Hh * Ff / 4 + 255) / 256, 256>>>(fc2w, 2, Ff, Ee * Hh * Ff / 4);

    zero_counts_kernel<<<1, 32>>>();
    router_kernel<<<T / 8, 256>>>(x, rw, out_probs, out_idx);
    scan_kernel<<<1, 1>>>();
    scatter_kernel<<<T / 256, 256>>>();

    // worst-case m-tiles: sum_e ceil(cnt_e/128) <= 128 + 8 = 136
    moe_gemm_mma<Hh, Ff, true ><<<136 * (Ff / 256), 256, SMEM_TOT>>>(fc1b);
    moe_gemm_mma<Ff, Hh, false><<<136 * (Hh / 256), 256, SMEM_TOT>>>(fc2b);

    combine_kernel<<<T, 128>>>(out);
}

// round 13
// speedup vs baseline: 3.3462x; 1.0078x over previous
#include <cuda_runtime.h>
#include <cuda_bf16.h>
#include <math.h>
#include <stdint.h>

// ---------------------------------------------------------------- constants
#define T   8192         // tokens (B*S)
#define Hh  512
#define Ff  2048
#define Ee  8
#define TK  16384        // T*K slots

// ---------------------------------------------------------------- scratch
// hi/lo split layouts: row = [hi(0..K-1) | lo(K..2K-1)]
__device__ __nv_bfloat16 g_xb [(size_t)T  * 2 * Hh];       // x split
__device__ __nv_bfloat16 g_w1b[(size_t)Ee * Ff * 2 * Hh];  // fc1_w split
__device__ __nv_bfloat16 g_w2b[(size_t)Ee * Hh * 2 * Ff];  // fc2_w split
__device__ __nv_bfloat16 g_act[(size_t)TK * 2 * Ff];       // gelu acts split
__device__ float g_y[(size_t)TK * Hh];
__device__ float g_topk_p[TK];
__device__ int   g_topk_i[TK];
__device__ int   g_counts[Ee];
__device__ int   g_run[Ee];
__device__ int   g_perm[TK];

// ---------------------------------------------------------------- PTX utils
__device__ __forceinline__ uint32_t smem_u32(const void* p) {
    uint32_t a;
    asm("{ .reg .u64 t; cvta.to.shared.u64 t, %1; cvt.u32.u64 %0, t; }"
        : "=r"(a) : "l"(p));
    return a;
}
__device__ __forceinline__ void cp_async16(uint32_t dst, const void* src, int sz) {
    asm volatile("cp.async.cg.shared.global [%0], [%1], 16, %2;"
                 :: "r"(dst), "l"(src), "r"(sz));
}
#define CP_COMMIT()  asm volatile("cp.async.commit_group;" ::: "memory")
#define CP_WAIT1()   asm volatile("cp.async.wait_group 1;" ::: "memory")

#define LDSM4(r0, r1, r2, r3, addr) \
    asm volatile("ldmatrix.sync.aligned.m8n8.x4.shared.b16 {%0,%1,%2,%3},[%4];" \
                 : "=r"(r0), "=r"(r1), "=r"(r2), "=r"(r3) : "r"(addr))

#define MMA16816(d, a, b0v, b1v) \
    asm volatile("mma.sync.aligned.m16n8k16.row.col.f32.bf16.bf16.f32 " \
                 "{%0,%1,%2,%3},{%4,%5,%6,%7},{%8,%9},{%0,%1,%2,%3};" \
                 : "+f"((d)[0]), "+f"((d)[1]), "+f"((d)[2]), "+f"((d)[3]) \
                 : "r"((a)[0]), "r"((a)[1]), "r"((a)[2]), "r"((a)[3]), \
                   "r"(b0v), "r"(b1v))

// ---------------------------------------------------------------- fused prep
// Zeroes per-expert counters and performs all three fp32 -> bf16 hi/lo split
// conversions in ONE launch (destinations are __device__ globals resolved in
// device code — host-side symbol use hits the ATS host-shadow address).
__device__ __forceinline__ void conv_one(const float* __restrict__ src,
                                         __nv_bfloat16* __restrict__ dst,
                                         int K, int q) {
    int K4 = K >> 2;
    int row = q / K4, c = q - row * K4;
    float4 v = ((const float4*)src)[q];
    __nv_bfloat16 h0 = __float2bfloat16_rn(v.x);
    __nv_bfloat16 h1 = __float2bfloat16_rn(v.y);
    __nv_bfloat16 h2 = __float2bfloat16_rn(v.z);
    __nv_bfloat16 h3 = __float2bfloat16_rn(v.w);
    __nv_bfloat16 l0 = __float2bfloat16_rn(v.x - __bfloat162float(h0));
    __nv_bfloat16 l1 = __float2bfloat16_rn(v.y - __bfloat162float(h1));
    __nv_bfloat16 l2 = __float2bfloat16_rn(v.z - __bfloat162float(h2));
    __nv_bfloat16 l3 = __float2bfloat16_rn(v.w - __bfloat162float(h3));
    __nv_bfloat16 hp[4] = {h0, h1, h2, h3};
    __nv_bfloat16 lp[4] = {l0, l1, l2, l3};
    __nv_bfloat16* base = dst + (size_t)row * 2 * K + c * 4;
    *(uint2*)base       = *(uint2*)hp;
    *(uint2*)(base + K) = *(uint2*)lp;
}

static constexpr int N4_X  = T * Hh / 4;            // 1048576
static constexpr int N4_W1 = Ee * Ff * Hh / 4;      // 2097152
static constexpr int N4_W2 = Ee * Hh * Ff / 4;      // 2097152
static constexpr int N4_TOT = N4_X + N4_W1 + N4_W2;

__global__ void fused_prep(const float* __restrict__ x,
                           const float* __restrict__ w1,
                           const float* __restrict__ w2) {
    int q = blockIdx.x * 256 + threadIdx.x;
    if (q < Ee) { g_counts[q] = 0; g_run[q] = 0; }
    if (q >= N4_TOT) return;
    if (q < N4_X)                 conv_one(x,  g_xb,  Hh, q);
    else if (q < N4_X + N4_W1)    conv_one(w1, g_w1b, Hh, q - N4_X);
    else                          conv_one(w2, g_w2b, Ff, q - N4_X - N4_W1);
}

// ---------------------------------------------------------------- router
__global__ void router_kernel(const float* __restrict__ x,
                              const float* __restrict__ rw,
                              float* __restrict__ out_probs,
                              float* __restrict__ out_idx) {
    __shared__ float rws[Ee * Hh];
    int tid = threadIdx.x;
    for (int i = tid; i < Ee * Hh; i += 256) rws[i] = rw[i];
    __syncthreads();

    int warp = tid >> 5, lane = tid & 31;
    int t = blockIdx.x * 8 + warp;
    const float* xr = x + (size_t)t * Hh;

    float xv[16];
#pragma unroll
    for (int j = 0; j < 16; ++j) xv[j] = xr[lane + 32 * j];

    float logit[Ee];
#pragma unroll
    for (int e = 0; e < Ee; ++e) {
        float acc = 0.f;
#pragma unroll
        for (int j = 0; j < 16; ++j) acc += xv[j] * rws[e * Hh + lane + 32 * j];
#pragma unroll
        for (int o = 16; o; o >>= 1) acc += __shfl_xor_sync(0xffffffffu, acc, o);
        logit[e] = acc;
    }

    if (lane == 0) {
        float mx = logit[0];
#pragma unroll
        for (int e = 1; e < Ee; ++e) mx = fmaxf(mx, logit[e]);
        float p[Ee], den = 0.f;
#pragma unroll
        for (int e = 0; e < Ee; ++e) { p[e] = expf(logit[e] - mx); den += p[e]; }
        float inv = 1.f / den;

        int i0 = 0;
#pragma unroll
        for (int e = 1; e < Ee; ++e) if (p[e] > p[i0]) i0 = e;
        int i1 = (i0 == 0) ? 1 : 0;
#pragma unroll
        for (int e = 0; e < Ee; ++e) if (e != i0 && p[e] > p[i1]) i1 = e;

        float p0 = p[i0] * inv, p1 = p[i1] * inv;
        float rden = 1.f / (p0 + p1 + 1e-9f);

#pragma unroll
        for (int e = 0; e < Ee; ++e) out_probs[(size_t)t * Ee + e] = p[e] * inv;
        out_idx[2 * t + 0] = (float)i0;
        out_idx[2 * t + 1] = (float)i1;
        g_topk_p[2 * t + 0] = p0 * rden;
        g_topk_p[2 * t + 1] = p1 * rden;
        g_topk_i[2 * t + 0] = i0;
        g_topk_i[2 * t + 1] = i1;
        atomicAdd(&g_counts[i0], 1);
        atomicAdd(&g_counts[i1], 1);
    }
}

// ---------------------------------------------------------------- scatter
// Offsets derived inline from finalized g_counts (scan kernel eliminated).
__global__ void scatter_kernel() {
    int t = blockIdx.x * 256 + threadIdx.x;
    if (t >= T) return;
    int offs[Ee];
    {
        int a = 0;
#pragma unroll
        for (int e = 0; e < Ee; ++e) { offs[e] = a; a += g_counts[e]; }
    }
#pragma unroll
    for (int k = 0; k < 2; ++k) {
        int e = g_topk_i[2 * t + k];
        int pos = atomicAdd(&g_run[e], 1);
        g_perm[offs[e] + pos] = 2 * t + k;
    }
}

// ---------------------------------------------------------------- HMMA GEMM
// CTA tile 128x256, warp tile 64x64 (warp grid 2x4), BK=32 source-K/stage.
// hi/lo split, 3 mma terms per k16 (AhBh + AlBh + AhBl).
// 3-stage cp.async pipeline; fragments via ldmatrix.x4.
// Stage layout (80B row stride, conflict-free): Ah[128] Al[128] Bh[256] Bl[256].
static constexpr int STAGE_B  = (2 * 128 + 2 * 256) * 80;   // 61440 bytes
static constexpr int SMEM_TOT = 3 * STAGE_B + 512;          // + slot array

template <int KSRC, int NDIM, bool G1>
__global__ void __launch_bounds__(256, 1)
moe_gemm_mma(const float* __restrict__ bias_all) {
    constexpr int NT  = NDIM / 256;
    constexpr int NKB = KSRC / 32;

    // expert offsets from g_counts (inline scan; g_offs eliminated)
    int cnts[Ee];
#pragma unroll
    for (int ee = 0; ee < Ee; ++ee) cnts[ee] = g_counts[ee];

    // block -> (expert, m-tile, n-tile)
    int b = blockIdx.x;
    int e = -1, mt = 0, nt = 0, acc0 = 0, ebase = 0, pre = 0;
    for (int ee = 0; ee < Ee; ++ee) {
        int mts = (cnts[ee] + 127) >> 7;
        int tot = mts * NT;
        if (b < acc0 + tot) { e = ee; ebase = pre; int loc = b - acc0; mt = loc / NT; nt = loc % NT; break; }
        acc0 += tot;
        pre  += cnts[ee];
    }
    if (e < 0) return;

    extern __shared__ char smem[];
    uint32_t smb = smem_u32(smem);
    int* s_slot = (int*)(smem + 3 * STAGE_B);
    int tid = threadIdx.x, wid = tid >> 5, lane = tid & 31;

    {
        int base = ebase + mt * 128, end = ebase + cnts[e];
        if (tid < 128) {
            int r = base + tid;
            s_slot[tid] = (r < end) ? g_perm[r] : -1;
        }
    }
    __syncthreads();

    const __nv_bfloat16* Wb =
        (G1 ? g_w1b : g_w2b) + ((size_t)e * NDIM + (size_t)nt * 256) * (2 * KSRC);

    // stage loader: 3072 16B chunks -> 12 per thread
    auto issue_stage = [&](int kb, int stg) {
        int k0 = kb * 32;
        uint32_t sb = smb + stg * STAGE_B;
#pragma unroll
        for (int i = 0; i < 12; ++i) {
            int q = i * 256 + tid;
            if (q < 1024) {                       // A tiles (hi, lo)
                int half = q >> 9;
                int rem = q & 511;
                int r = rem >> 2, c = rem & 3;
                uint32_t dst = sb + half * 10240 + r * 80 + c * 16;
                int slot = s_slot[r];
                if (slot >= 0) {
                    const __nv_bfloat16* rowp =
                        G1 ? (g_xb + (size_t)(slot >> 1) * (2 * KSRC))
                           : (g_act + (size_t)slot * (2 * KSRC));
                    cp_async16(dst, rowp + half * KSRC + k0 + c * 8, 16);
                } else {
                    cp_async16(dst, g_xb, 0);     // zero-fill
                }
            } else {                              // B tiles (hi, lo)
                int idx = q - 1024;
                int half = idx >> 10;
                int rem = idx & 1023;
                int r = rem >> 2, c = rem & 3;
                uint32_t dst = sb + 20480 + half * 20480 + r * 80 + c * 16;
                cp_async16(dst, Wb + (size_t)r * (2 * KSRC) + half * KSRC + k0 + c * 8, 16);
            }
        }
        CP_COMMIT();
    };

    int warp_m = wid >> 2, warp_n = wid & 3;
    float accv[4][8][4];
#pragma unroll
    for (int mi = 0; mi < 4; ++mi)
#pragma unroll
        for (int ni = 0; ni < 8; ++ni)
#pragma unroll
            for (int j = 0; j < 4; ++j) accv[mi][ni][j] = 0.f;

    // ldmatrix lane address components
    uint32_t lmrow = lane & 15;
    uint32_t lkc16 = (lane >> 4) * 16;

    issue_stage(0, 0);
    issue_stage(1, 1);

    for (int kb = 0; kb < NKB; ++kb) {
        CP_WAIT1();
        __syncthreads();
        uint32_t sb = smb + (kb % 3) * STAGE_B;
#pragma unroll
        for (int kk = 0; kk < 2; ++kk) {
            uint32_t ah[4][4], al[4][4], bh[8][2], bl[8][2];
            uint32_t aaddr = sb + (warp_m * 64 + lmrow) * 80 + kk * 32 + lkc16;
            uint32_t baddr = sb + 20480 + (warp_n * 64 + lmrow) * 80 + kk * 32 + lkc16;
#pragma unroll
            for (int mi = 0; mi < 4; ++mi) {
                LDSM4(ah[mi][0], ah[mi][1], ah[mi][2], ah[mi][3], aaddr + mi * 1280);
                LDSM4(al[mi][0], al[mi][1], al[mi][2], al[mi][3], aaddr + 10240 + mi * 1280);
            }
#pragma unroll
            for (int p = 0; p < 4; ++p)
                LDSM4(bh[2 * p][0], bh[2 * p + 1][0], bh[2 * p][1], bh[2 * p + 1][1],
                      baddr + p * 1280);
#pragma unroll
            for (int mi = 0; mi < 4; ++mi)
#pragma unroll
                for (int ni = 0; ni < 8; ++ni) {
                    MMA16816(accv[mi][ni], ah[mi], bh[ni][0], bh[ni][1]);
                    MMA16816(accv[mi][ni], al[mi], bh[ni][0], bh[ni][1]);
                }
#pragma unroll
            for (int p = 0; p < 4; ++p)
                LDSM4(bl[2 * p][0], bl[2 * p + 1][0], bl[2 * p][1], bl[2 * p + 1][1],
                      baddr + 20480 + p * 1280);
#pragma unroll
            for (int mi = 0; mi < 4; ++mi)
#pragma unroll
                for (int ni = 0; ni < 8; ++ni)
                    MMA16816(accv[mi][ni], ah[mi], bl[ni][0], bl[ni][1]);
        }
        if (kb + 2 < NKB) issue_stage(kb + 2, (kb + 2) % 3);
        else CP_COMMIT();
    }

    // ------------------------------------------------------------ epilogue
    int colb = nt * 256 + warp_n * 64 + 2 * (lane & 3);
    float2 bb[8];
#pragma unroll
    for (int ni = 0; ni < 8; ++ni) {
        bb[ni].x = bias_all[(size_t)e * NDIM + colb + ni * 8];
        bb[ni].y = bias_all[(size_t)e * NDIM + colb + ni * 8 + 1];
    }
#pragma unroll
    for (int mi = 0; mi < 4; ++mi) {
#pragma unroll
        for (int h = 0; h < 2; ++h) {
            int row = warp_m * 64 + mi * 16 + (lane >> 2) + h * 8;
            int slot = s_slot[row];
            if (slot < 0) continue;
            if (G1) {
                __nv_bfloat16* rowp = g_act + (size_t)slot * (2 * Ff);
#pragma unroll
                for (int ni = 0; ni < 8; ++ni) {
                    int n = colb + ni * 8;
                    float v0 = accv[mi][ni][2 * h + 0] + bb[ni].x;
                    float v1 = accv[mi][ni][2 * h + 1] + bb[ni].y;
                    v0 = 0.5f * v0 * (1.f + erff(v0 * 0.70710678118654752f));
                    v1 = 0.5f * v1 * (1.f + erff(v1 * 0.70710678118654752f));
                    __nv_bfloat16 h0 = __float2bfloat16_rn(v0);
                    __nv_bfloat16 h1 = __float2bfloat16_rn(v1);
                    __nv_bfloat16 l0 = __float2bfloat16_rn(v0 - __bfloat162float(h0));
                    __nv_bfloat16 l1 = __float2bfloat16_rn(v1 - __bfloat162float(h1));
                    __nv_bfloat16 hp[2] = {h0, h1};
                    __nv_bfloat16 lp[2] = {l0, l1};
                    *(uint32_t*)(rowp + n)      = *(uint32_t*)hp;
                    *(uint32_t*)(rowp + Ff + n) = *(uint32_t*)lp;
                }
            } else {
                float* rowp = g_y + (size_t)slot * Hh;
#pragma unroll
                for (int ni = 0; ni < 8; ++ni) {
                    int n = colb + ni * 8;
                    float2 v;
                    v.x = accv[mi][ni][2 * h + 0] + bb[ni].x;
                    v.y = accv[mi][ni][2 * h + 1] + bb[ni].y;
                    *(float2*)(rowp + n) = v;
                }
            }
        }
    }
}

// ---------------------------------------------------------------- combine
__global__ void combine_kernel(float* __restrict__ out) {
    int t = blockIdx.x;
    float p0 = g_topk_p[2 * t], p1 = g_topk_p[2 * t + 1];
    const float4* y0 = (const float4*)(g_y + (size_t)(2 * t) * Hh);
    const float4* y1 = (const float4*)(g_y + (size_t)(2 * t + 1) * Hh);
    float4* o = (float4*)(out + (size_t)t * Hh);
    int i = threadIdx.x;
    float4 a = y0[i], b = y1[i];
    o[i] = make_float4(p0 * a.x + p1 * b.x, p0 * a.y + p1 * b.y,
                       p0 * a.z + p1 * b.z, p0 * a.w + p1 * b.w);
}

// ---------------------------------------------------------------- launch
extern "C" void kernel_launch(void* const* d_in, const int* in_sizes, int n_in,
                              void* d_out, int out_size) {
    (void)in_sizes; (void)n_in; (void)out_size;
    const float* x    = (const float*)d_in[0];
    const float* rw   = (const float*)d_in[1];
    const float* fc1w = (const float*)d_in[2];
    const float* fc1b = (const float*)d_in[3];
    const float* fc2w = (const float*)d_in[4];
    const float* fc2b = (const float*)d_in[5];

    float* out       = (float*)d_out;                 // [T, Hh]
    float* out_probs = out + (size_t)T * Hh;          // [T, Ee]
    float* out_idx   = out_probs + (size_t)T * Ee;    // [T, 2] as float

    cudaFuncSetAttribute(moe_gemm_mma<Hh, Ff, true>,
                         cudaFuncAttributeMaxDynamicSharedMemorySize, SMEM_TOT);
    cudaFuncSetAttribute(moe_gemm_mma<Ff, Hh, false>,
                         cudaFuncAttributeMaxDynamicSharedMemorySize, SMEM_TOT);

    // 1: conversions + counter zeroing (fused)
    fused_prep<<<(N4_TOT + 255) / 256, 256>>>(x, fc1w, fc2w);
    // 2: router
    router_kernel<<<T / 8, 256>>>(x, rw, out_probs, out_idx);
    // 3: scatter (inline scan)
    scatter_kernel<<<T / 256, 256>>>();
    // 4: GEMM1 — the ncu-profiled launch
    moe_gemm_mma<Hh, Ff, true ><<<136 * (Ff / 256), 256, SMEM_TOT>>>(fc1b);
    // 5: GEMM2
    moe_gemm_mma<Ff, Hh, false><<<136 * (Hh / 256), 256, SMEM_TOT>>>(fc2b);
    // 6: combine
    combine_kernel<<<T, 128>>>(out);
}

// round 14
// speedup vs baseline: 3.4415x; 1.0285x over previous
#include <cuda_runtime.h>
#include <cuda_bf16.h>
#include <math.h>
#include <stdint.h>

// ---------------------------------------------------------------- constants
#define T   8192         // tokens (B*S)
#define Hh  512
#define Ff  2048
#define Ee  8
#define TK  16384        // T*K slots

// ---------------------------------------------------------------- scratch
// hi/lo split layouts: row = [hi(0..K-1) | lo(K..2K-1)]
__device__ __nv_bfloat16 g_xb [(size_t)T  * 2 * Hh];       // x split
__device__ __nv_bfloat16 g_w1b[(size_t)Ee * Ff * 2 * Hh];  // fc1_w split
__device__ __nv_bfloat16 g_w2b[(size_t)Ee * Hh * 2 * Ff];  // fc2_w split
__device__ __nv_bfloat16 g_act[(size_t)TK * 2 * Ff];       // gelu acts split
__device__ float g_y[(size_t)TK * Hh];
__device__ float g_topk_p[TK];
__device__ int   g_topk_i[TK];
__device__ int   g_counts[Ee];
__device__ int   g_run[Ee];
__device__ int   g_perm[TK];

// ---------------------------------------------------------------- PTX utils
__device__ __forceinline__ uint32_t smem_u32(const void* p) {
    uint32_t a;
    asm("{ .reg .u64 t; cvta.to.shared.u64 t, %1; cvt.u32.u64 %0, t; }"
        : "=r"(a) : "l"(p));
    return a;
}
__device__ __forceinline__ void cp_async16(uint32_t dst, const void* src, int sz) {
    asm volatile("cp.async.cg.shared.global [%0], [%1], 16, %2;"
                 :: "r"(dst), "l"(src), "r"(sz));
}
#define CP_COMMIT()  asm volatile("cp.async.commit_group;" ::: "memory")
#define CP_WAIT1()   asm volatile("cp.async.wait_group 1;" ::: "memory")

#define LDSM4(r0, r1, r2, r3, addr) \
    asm volatile("ldmatrix.sync.aligned.m8n8.x4.shared.b16 {%0,%1,%2,%3},[%4];" \
                 : "=r"(r0), "=r"(r1), "=r"(r2), "=r"(r3) : "r"(addr))

#define MMA16816(d, a, b0v, b1v) \
    asm volatile("mma.sync.aligned.m16n8k16.row.col.f32.bf16.bf16.f32 " \
                 "{%0,%1,%2,%3},{%4,%5,%6,%7},{%8,%9},{%0,%1,%2,%3};" \
                 : "+f"((d)[0]), "+f"((d)[1]), "+f"((d)[2]), "+f"((d)[3]) \
                 : "r"((a)[0]), "r"((a)[1]), "r"((a)[2]), "r"((a)[3]), \
                   "r"(b0v), "r"(b1v))

// ---------------------------------------------------------------- fused prep
__device__ __forceinline__ void conv_one(const float* __restrict__ src,
                                         __nv_bfloat16* __restrict__ dst,
                                         int K, int q) {
    int K4 = K >> 2;
    int row = q / K4, c = q - row * K4;
    float4 v = ((const float4*)src)[q];
    __nv_bfloat16 h0 = __float2bfloat16_rn(v.x);
    __nv_bfloat16 h1 = __float2bfloat16_rn(v.y);
    __nv_bfloat16 h2 = __float2bfloat16_rn(v.z);
    __nv_bfloat16 h3 = __float2bfloat16_rn(v.w);
    __nv_bfloat16 l0 = __float2bfloat16_rn(v.x - __bfloat162float(h0));
    __nv_bfloat16 l1 = __float2bfloat16_rn(v.y - __bfloat162float(h1));
    __nv_bfloat16 l2 = __float2bfloat16_rn(v.z - __bfloat162float(h2));
    __nv_bfloat16 l3 = __float2bfloat16_rn(v.w - __bfloat162float(h3));
    __nv_bfloat16 hp[4] = {h0, h1, h2, h3};
    __nv_bfloat16 lp[4] = {l0, l1, l2, l3};
    __nv_bfloat16* base = dst + (size_t)row * 2 * K + c * 4;
    *(uint2*)base       = *(uint2*)hp;
    *(uint2*)(base + K) = *(uint2*)lp;
}

static constexpr int N4_X  = T * Hh / 4;
static constexpr int N4_W1 = Ee * Ff * Hh / 4;
static constexpr int N4_W2 = Ee * Hh * Ff / 4;
static constexpr int N4_TOT = N4_X + N4_W1 + N4_W2;

__global__ void fused_prep(const float* __restrict__ x,
                           const float* __restrict__ w1,
                           const float* __restrict__ w2) {
    int q = blockIdx.x * 256 + threadIdx.x;
    if (q < Ee) { g_counts[q] = 0; g_run[q] = 0; }
    if (q >= N4_TOT) return;
    if (q < N4_X)                 conv_one(x,  g_xb,  Hh, q);
    else if (q < N4_X + N4_W1)    conv_one(w1, g_w1b, Hh, q - N4_X);
    else                          conv_one(w2, g_w2b, Ff, q - N4_X - N4_W1);
}

// ---------------------------------------------------------------- router
__global__ void router_kernel(const float* __restrict__ x,
                              const float* __restrict__ rw,
                              float* __restrict__ out_probs,
                              float* __restrict__ out_idx) {
    __shared__ float rws[Ee * Hh];
    int tid = threadIdx.x;
    for (int i = tid; i < Ee * Hh; i += 256) rws[i] = rw[i];
    __syncthreads();

    int warp = tid >> 5, lane = tid & 31;
    int t = blockIdx.x * 8 + warp;
    const float* xr = x + (size_t)t * Hh;

    float xv[16];
#pragma unroll
    for (int j = 0; j < 16; ++j) xv[j] = xr[lane + 32 * j];

    float logit[Ee];
#pragma unroll
    for (int e = 0; e < Ee; ++e) {
        float acc = 0.f;
#pragma unroll
        for (int j = 0; j < 16; ++j) acc += xv[j] * rws[e * Hh + lane + 32 * j];
#pragma unroll
        for (int o = 16; o; o >>= 1) acc += __shfl_xor_sync(0xffffffffu, acc, o);
        logit[e] = acc;
    }

    if (lane == 0) {
        float mx = logit[0];
#pragma unroll
        for (int e = 1; e < Ee; ++e) mx = fmaxf(mx, logit[e]);
        float p[Ee], den = 0.f;
#pragma unroll
        for (int e = 0; e < Ee; ++e) { p[e] = expf(logit[e] - mx); den += p[e]; }
        float inv = 1.f / den;

        int i0 = 0;
#pragma unroll
        for (int e = 1; e < Ee; ++e) if (p[e] > p[i0]) i0 = e;
        int i1 = (i0 == 0) ? 1 : 0;
#pragma unroll
        for (int e = 0; e < Ee; ++e) if (e != i0 && p[e] > p[i1]) i1 = e;

        float p0 = p[i0] * inv, p1 = p[i1] * inv;
        float rden = 1.f / (p0 + p1 + 1e-9f);

#pragma unroll
        for (int e = 0; e < Ee; ++e) out_probs[(size_t)t * Ee + e] = p[e] * inv;
        out_idx[2 * t + 0] = (float)i0;
        out_idx[2 * t + 1] = (float)i1;
        g_topk_p[2 * t + 0] = p0 * rden;
        g_topk_p[2 * t + 1] = p1 * rden;
        g_topk_i[2 * t + 0] = i0;
        g_topk_i[2 * t + 1] = i1;
        atomicAdd(&g_counts[i0], 1);
        atomicAdd(&g_counts[i1], 1);
    }
}

// ---------------------------------------------------------------- scatter
__global__ void scatter_kernel() {
    int t = blockIdx.x * 256 + threadIdx.x;
    if (t >= T) return;
    int offs[Ee];
    {
        int a = 0;
#pragma unroll
        for (int e = 0; e < Ee; ++e) { offs[e] = a; a += g_counts[e]; }
    }
#pragma unroll
    for (int k = 0; k < 2; ++k) {
        int e = g_topk_i[2 * t + k];
        int pos = atomicAdd(&g_run[e], 1);
        g_perm[offs[e] + pos] = 2 * t + k;
    }
}

// ---------------------------------------------------------------- HMMA GEMM
// CTA tile 128x256, 512 threads, warp grid 2x8, warp tile 64x32.
// (R13 profile: tensor=45%, occ=12.4% -> latency-bound with 2 warps/SMSP.
//  16 warps = 4/SMSP for latency hiding; numerics & k-order unchanged.)
// hi/lo split, 3 mma terms per k16 (AhBh + AlBh + AhBl), 3-stage cp.async.
// Stage layout (80B row stride): Ah[128] Al[128] Bh[256] Bl[256].
static constexpr int STAGE_B  = (2 * 128 + 2 * 256) * 80;   // 61440 bytes
static constexpr int SMEM_TOT = 3 * STAGE_B + 512;          // + slot array

template <int KSRC, int NDIM, bool G1>
__global__ void __launch_bounds__(512, 1)
moe_gemm_mma(const float* __restrict__ bias_all) {
    constexpr int NT  = NDIM / 256;
    constexpr int NKB = KSRC / 32;

    int cnts[Ee];
#pragma unroll
    for (int ee = 0; ee < Ee; ++ee) cnts[ee] = g_counts[ee];

    // block -> (expert, m-tile, n-tile)
    int b = blockIdx.x;
    int e = -1, mt = 0, nt = 0, acc0 = 0, ebase = 0, pre = 0;
    for (int ee = 0; ee < Ee; ++ee) {
        int mts = (cnts[ee] + 127) >> 7;
        int tot = mts * NT;
        if (b < acc0 + tot) { e = ee; ebase = pre; int loc = b - acc0; mt = loc / NT; nt = loc % NT; break; }
        acc0 += tot;
        pre  += cnts[ee];
    }
    if (e < 0) return;

    extern __shared__ char smem[];
    uint32_t smb = smem_u32(smem);
    int* s_slot = (int*)(smem + 3 * STAGE_B);
    int tid = threadIdx.x, wid = tid >> 5, lane = tid & 31;

    {
        int base = ebase + mt * 128, end = ebase + cnts[e];
        if (tid < 128) {
            int r = base + tid;
            s_slot[tid] = (r < end) ? g_perm[r] : -1;
        }
    }
    __syncthreads();

    const __nv_bfloat16* Wb =
        (G1 ? g_w1b : g_w2b) + ((size_t)e * NDIM + (size_t)nt * 256) * (2 * KSRC);

    // stage loader: 3072 16B chunks -> 6 per thread
    auto issue_stage = [&](int kb, int stg) {
        int k0 = kb * 32;
        uint32_t sb = smb + stg * STAGE_B;
#pragma unroll
        for (int i = 0; i < 6; ++i) {
            int q = i * 512 + tid;
            if (q < 1024) {                       // A tiles (hi, lo)
                int half = q >> 9;
                int rem = q & 511;
                int r = rem >> 2, c = rem & 3;
                uint32_t dst = sb + half * 10240 + r * 80 + c * 16;
                int slot = s_slot[r];
                if (slot >= 0) {
                    const __nv_bfloat16* rowp =
                        G1 ? (g_xb + (size_t)(slot >> 1) * (2 * KSRC))
                           : (g_act + (size_t)slot * (2 * KSRC));
                    cp_async16(dst, rowp + half * KSRC + k0 + c * 8, 16);
                } else {
                    cp_async16(dst, g_xb, 0);     // zero-fill
                }
            } else {                              // B tiles (hi, lo)
                int idx = q - 1024;
                int half = idx >> 10;
                int rem = idx & 1023;
                int r = rem >> 2, c = rem & 3;
                uint32_t dst = sb + 20480 + half * 20480 + r * 80 + c * 16;
                cp_async16(dst, Wb + (size_t)r * (2 * KSRC) + half * KSRC + k0 + c * 8, 16);
            }
        }
        CP_COMMIT();
    };

    int warp_m = wid >> 3, warp_n = wid & 7;    // 2 x 8 warp grid
    float accv[4][4][4];
#pragma unroll
    for (int mi = 0; mi < 4; ++mi)
#pragma unroll
        for (int ni = 0; ni < 4; ++ni)
#pragma unroll
            for (int j = 0; j < 4; ++j) accv[mi][ni][j] = 0.f;

    uint32_t lmrow = lane & 15;
    uint32_t lkc16 = (lane >> 4) * 16;

    issue_stage(0, 0);
    issue_stage(1, 1);

    for (int kb = 0; kb < NKB; ++kb) {
        CP_WAIT1();
        __syncthreads();
        uint32_t sb = smb + (kb % 3) * STAGE_B;
#pragma unroll
        for (int kk = 0; kk < 2; ++kk) {
            uint32_t ah[4][4], al[4][4], bh[4][2], bl[4][2];
            uint32_t aaddr = sb + (warp_m * 64 + lmrow) * 80 + kk * 32 + lkc16;
            uint32_t baddr = sb + 20480 + (warp_n * 32 + lmrow) * 80 + kk * 32 + lkc16;
#pragma unroll
            for (int mi = 0; mi < 4; ++mi) {
                LDSM4(ah[mi][0], ah[mi][1], ah[mi][2], ah[mi][3], aaddr + mi * 1280);
                LDSM4(al[mi][0], al[mi][1], al[mi][2], al[mi][3], aaddr + 10240 + mi * 1280);
            }
#pragma unroll
            for (int p = 0; p < 2; ++p)
                LDSM4(bh[2 * p][0], bh[2 * p + 1][0], bh[2 * p][1], bh[2 * p + 1][1],
                      baddr + p * 1280);
#pragma unroll
            for (int mi = 0; mi < 4; ++mi)
#pragma unroll
                for (int ni = 0; ni < 4; ++ni) {
                    MMA16816(accv[mi][ni], ah[mi], bh[ni][0], bh[ni][1]);
                    MMA16816(accv[mi][ni], al[mi], bh[ni][0], bh[ni][1]);
                }
#pragma unroll
            for (int p = 0; p < 2; ++p)
                LDSM4(bl[2 * p][0], bl[2 * p + 1][0], bl[2 * p][1], bl[2 * p + 1][1],
                      baddr + 20480 + p * 1280);
#pragma unroll
            for (int mi = 0; mi < 4; ++mi)
#pragma unroll
                for (int ni = 0; ni < 4; ++ni)
                    MMA16816(accv[mi][ni], ah[mi], bl[ni][0], bl[ni][1]);
        }
        if (kb + 2 < NKB) issue_stage(kb + 2, (kb + 2) % 3);
        else CP_COMMIT();
    }

    // ------------------------------------------------------------ epilogue
    int colb = nt * 256 + warp_n * 32 + 2 * (lane & 3);
    float2 bb[4];
#pragma unroll
    for (int ni = 0; ni < 4; ++ni) {
        bb[ni].x = bias_all[(size_t)e * NDIM + colb + ni * 8];
        bb[ni].y = bias_all[(size_t)e * NDIM + colb + ni * 8 + 1];
    }
#pragma unroll
    for (int mi = 0; mi < 4; ++mi) {
#pragma unroll
        for (int h = 0; h < 2; ++h) {
            int row = warp_m * 64 + mi * 16 + (lane >> 2) + h * 8;
            int slot = s_slot[row];
            if (slot < 0) continue;
            if (G1) {
                __nv_bfloat16* rowp = g_act + (size_t)slot * (2 * Ff);
#pragma unroll
                for (int ni = 0; ni < 4; ++ni) {
                    int n = colb + ni * 8;
                    float v0 = accv[mi][ni][2 * h + 0] + bb[ni].x;
                    float v1 = accv[mi][ni][2 * h + 1] + bb[ni].y;
                    v0 = 0.5f * v0 * (1.f + erff(v0 * 0.70710678118654752f));
                    v1 = 0.5f * v1 * (1.f + erff(v1 * 0.70710678118654752f));
                    __nv_bfloat16 h0 = __float2bfloat16_rn(v0);
                    __nv_bfloat16 h1 = __float2bfloat16_rn(v1);
                    __nv_bfloat16 l0 = __float2bfloat16_rn(v0 - __bfloat162float(h0));
                    __nv_bfloat16 l1 = __float2bfloat16_rn(v1 - __bfloat162float(h1));
                    __nv_bfloat16 hp[2] = {h0, h1};
                    __nv_bfloat16 lp[2] = {l0, l1};
                    *(uint32_t*)(rowp + n)      = *(uint32_t*)hp;
                    *(uint32_t*)(rowp + Ff + n) = *(uint32_t*)lp;
                }
            } else {
                float* rowp = g_y + (size_t)slot * Hh;
#pragma unroll
                for (int ni = 0; ni < 4; ++ni) {
                    int n = colb + ni * 8;
                    float2 v;
                    v.x = accv[mi][ni][2 * h + 0] + bb[ni].x;
                    v.y = accv[mi][ni][2 * h + 1] + bb[ni].y;
                    *(float2*)(rowp + n) = v;
                }
            }
        }
    }
}

// ---------------------------------------------------------------- combine
__global__ void combine_kernel(float* __restrict__ out) {
    int t = blockIdx.x;
    float p0 = g_topk_p[2 * t], p1 = g_topk_p[2 * t + 1];
    const float4* y0 = (const float4*)(g_y + (size_t)(2 * t) * Hh);
    const float4* y1 = (const float4*)(g_y + (size_t)(2 * t + 1) * Hh);
    float4* o = (float4*)(out + (size_t)t * Hh);
    int i = threadIdx.x;
    float4 a = y0[i], b = y1[i];
    o[i] = make_float4(p0 * a.x + p1 * b.x, p0 * a.y + p1 * b.y,
                       p0 * a.z + p1 * b.z, p0 * a.w + p1 * b.w);
}

// ---------------------------------------------------------------- launch
extern "C" void kernel_launch(void* const* d_in, const int* in_sizes, int n_in,
                              void* d_out, int out_size) {
    (void)in_sizes; (void)n_in; (void)out_size;
    const float* x    = (const float*)d_in[0];
    const float* rw   = (const float*)d_in[1];
    const float* fc1w = (const float*)d_in[2];
    const float* fc1b = (const float*)d_in[3];
    const float* fc2w = (const float*)d_in[4];
    const float* fc2b = (const float*)d_in[5];

    float* out       = (float*)d_out;                 // [T, Hh]
    float* out_probs = out + (size_t)T * Hh;          // [T, Ee]
    float* out_idx   = out_probs + (size_t)T * Ee;    // [T, 2] as float

    cudaFuncSetAttribute(moe_gemm_mma<Hh, Ff, true>,
                         cudaFuncAttributeMaxDynamicSharedMemorySize, SMEM_TOT);
    cudaFuncSetAttribute(moe_gemm_mma<Ff, Hh, false>,
                         cudaFuncAttributeMaxDynamicSharedMemorySize, SMEM_TOT);

    // 1: conversions + counter zeroing (fused)
    fused_prep<<<(N4_TOT + 255) / 256, 256>>>(x, fc1w, fc2w);
    // 2: router
    router_kernel<<<T / 8, 256>>>(x, rw, out_probs, out_idx);
    // 3: scatter (inline scan)
    scatter_kernel<<<T / 256, 256>>>();
    // 4: GEMM1 — the ncu-profiled launch
    moe_gemm_mma<Hh, Ff, true ><<<136 * (Ff / 256), 512, SMEM_TOT>>>(fc1b);
    // 5: GEMM2
    moe_gemm_mma<Ff, Hh, false><<<136 * (Hh / 256), 512, SMEM_TOT>>>(fc2b);
    // 6: combine
    combine_kernel<<<T, 128>>>(out);
}

// round 17
// speedup vs baseline: 3.5403x; 1.0287x over previous
#include <cuda_runtime.h>
#include <cuda_bf16.h>
#include <math.h>
#include <stdint.h>

// ---------------------------------------------------------------- constants
#define T   8192         // tokens (B*S)
#define Hh  512
#define Ff  2048
#define Ee  8
#define TK  16384        // T*K slots

// ---------------------------------------------------------------- scratch
__device__ __nv_bfloat16 g_xb [(size_t)T  * 2 * Hh];
__device__ __nv_bfloat16 g_w1b[(size_t)Ee * Ff * 2 * Hh];
__device__ __nv_bfloat16 g_w2b[(size_t)Ee * Hh * 2 * Ff];
__device__ __nv_bfloat16 g_act[(size_t)TK * 2 * Ff];
__device__ float g_y[(size_t)TK * Hh];
__device__ float g_topk_p[TK];
__device__ int   g_topk_i[TK];
__device__ int   g_counts[Ee];
__device__ int   g_run[Ee];
__device__ int   g_perm[TK];

// ---------------------------------------------------------------- PTX utils
__device__ __forceinline__ uint32_t smem_u32(const void* p) {
    uint32_t a;
    asm("{ .reg .u64 t; cvta.to.shared.u64 t, %1; cvt.u32.u64 %0, t; }"
        : "=r"(a) : "l"(p));
    return a;
}
__device__ __forceinline__ void cp_async16(uint32_t dst, const void* src, int sz) {
    asm volatile("cp.async.cg.shared.global [%0], [%1], 16, %2;"
                 :: "r"(dst), "l"(src), "r"(sz));
}
#define CP_COMMIT()  asm volatile("cp.async.commit_group;" ::: "memory")
#define CP_WAIT1()   asm volatile("cp.async.wait_group 1;" ::: "memory")

#define LDSM4(r0, r1, r2, r3, addr) \
    asm volatile("ldmatrix.sync.aligned.m8n8.x4.shared.b16 {%0,%1,%2,%3},[%4];" \
                 : "=r"(r0), "=r"(r1), "=r"(r2), "=r"(r3) : "r"(addr))

#define MMA16816(d, a, b0v, b1v) \
    asm volatile("mma.sync.aligned.m16n8k16.row.col.f32.bf16.bf16.f32 " \
                 "{%0,%1,%2,%3},{%4,%5,%6,%7},{%8,%9},{%0,%1,%2,%3};" \
                 : "+f"((d)[0]), "+f"((d)[1]), "+f"((d)[2]), "+f"((d)[3]) \
                 : "r"((a)[0]), "r"((a)[1]), "r"((a)[2]), "r"((a)[3]), \
                   "r"(b0v), "r"(b1v))

// ---------------------------------------------------------------- fused prep
__device__ __forceinline__ void conv_one(const float* __restrict__ src,
                                         __nv_bfloat16* __restrict__ dst,
                                         int K, int q) {
    int K4 = K >> 2;
    int row = q / K4, c = q - row * K4;
    float4 v = ((const float4*)src)[q];
    __nv_bfloat16 h0 = __float2bfloat16_rn(v.x);
    __nv_bfloat16 h1 = __float2bfloat16_rn(v.y);
    __nv_bfloat16 h2 = __float2bfloat16_rn(v.z);
    __nv_bfloat16 h3 = __float2bfloat16_rn(v.w);
    __nv_bfloat16 l0 = __float2bfloat16_rn(v.x - __bfloat162float(h0));
    __nv_bfloat16 l1 = __float2bfloat16_rn(v.y - __bfloat162float(h1));
    __nv_bfloat16 l2 = __float2bfloat16_rn(v.z - __bfloat162float(h2));
    __nv_bfloat16 l3 = __float2bfloat16_rn(v.w - __bfloat162float(h3));
    __nv_bfloat16 hp[4] = {h0, h1, h2, h3};
    __nv_bfloat16 lp[4] = {l0, l1, l2, l3};
    __nv_bfloat16* base = dst + (size_t)row * 2 * K + c * 4;
    *(uint2*)base       = *(uint2*)hp;
    *(uint2*)(base + K) = *(uint2*)lp;
}

static constexpr int N4_X  = T * Hh / 4;
static constexpr int N4_W1 = Ee * Ff * Hh / 4;
static constexpr int N4_W2 = Ee * Hh * Ff / 4;
static constexpr int N4_TOT = N4_X + N4_W1 + N4_W2;

__global__ void fused_prep(const float* __restrict__ x,
                           const float* __restrict__ w1,
                           const float* __restrict__ w2) {
    int q = blockIdx.x * 256 + threadIdx.x;
    if (q < Ee) { g_counts[q] = 0; g_run[q] = 0; }
    if (q >= N4_TOT) return;
    if (q < N4_X)                 conv_one(x,  g_xb,  Hh, q);
    else if (q < N4_X + N4_W1)    conv_one(w1, g_w1b, Hh, q - N4_X);
    else                          conv_one(w2, g_w2b, Ff, q - N4_X - N4_W1);
}

// ---------------------------------------------------------------- router
__global__ void router_kernel(const float* __restrict__ x,
                              const float* __restrict__ rw,
                              float* __restrict__ out_probs,
                              float* __restrict__ out_idx) {
    __shared__ float rws[Ee * Hh];
    int tid = threadIdx.x;
    for (int i = tid; i < Ee * Hh; i += 256) rws[i] = rw[i];
    __syncthreads();

    int warp = tid >> 5, lane = tid & 31;
    int t = blockIdx.x * 8 + warp;
    const float* xr = x + (size_t)t * Hh;

    float xv[16];
#pragma unroll
    for (int j = 0; j < 16; ++j) xv[j] = xr[lane + 32 * j];

    float logit[Ee];
#pragma unroll
    for (int e = 0; e < Ee; ++e) {
        float acc = 0.f;
#pragma unroll
        for (int j = 0; j < 16; ++j) acc += xv[j] * rws[e * Hh + lane + 32 * j];
#pragma unroll
        for (int o = 16; o; o >>= 1) acc += __shfl_xor_sync(0xffffffffu, acc, o);
        logit[e] = acc;
    }

    if (lane == 0) {
        float mx = logit[0];
#pragma unroll
        for (int e = 1; e < Ee; ++e) mx = fmaxf(mx, logit[e]);
        float p[Ee], den = 0.f;
#pragma unroll
        for (int e = 0; e < Ee; ++e) { p[e] = expf(logit[e] - mx); den += p[e]; }
        float inv = 1.f / den;

        int i0 = 0;
#pragma unroll
        for (int e = 1; e < Ee; ++e) if (p[e] > p[i0]) i0 = e;
        int i1 = (i0 == 0) ? 1 : 0;
#pragma unroll
        for (int e = 0; e < Ee; ++e) if (e != i0 && p[e] > p[i1]) i1 = e;

        float p0 = p[i0] * inv, p1 = p[i1] * inv;
        float rden = 1.f / (p0 + p1 + 1e-9f);

#pragma unroll
        for (int e = 0; e < Ee; ++e) out_probs[(size_t)t * Ee + e] = p[e] * inv;
        out_idx[2 * t + 0] = (float)i0;
        out_idx[2 * t + 1] = (float)i1;
        g_topk_p[2 * t + 0] = p0 * rden;
        g_topk_p[2 * t + 1] = p1 * rden;
        g_topk_i[2 * t + 0] = i0;
        g_topk_i[2 * t + 1] = i1;
        atomicAdd(&g_counts[i0], 1);
        atomicAdd(&g_counts[i1], 1);
    }
}

// ---------------------------------------------------------------- scatter
__global__ void scatter_kernel() {
    int t = blockIdx.x * 256 + threadIdx.x;
    if (t >= T) return;
    int offs[Ee];
    {
        int a = 0;
#pragma unroll
        for (int e = 0; e < Ee; ++e) { offs[e] = a; a += g_counts[e]; }
    }
#pragma unroll
    for (int k = 0; k < 2; ++k) {
        int e = g_topk_i[2 * t + k];
        int pos = atomicAdd(&g_run[e], 1);
        g_perm[offs[e] + pos] = 2 * t + k;
    }
}

// ---------------------------------------------------------------- HMMA GEMM
// CTA tile 128x128, 128 threads (4 warps, grid 2x2), warp tile 64x64.
// TWO CTAs per SM (launch_bounds(128,2)) so barrier/CP_WAIT stalls of one
// CTA overlap compute of the other (R13: same tile, 1 CTA -> 45% tensor;
// crossbar cap for 85B/MMA is 75%).
// 2-stage cp.async double buffer, BK=32; hi/lo split, 3 mma terms per k16.
// Stage layout (80B stride): Ah[128] Al[128] Bh[128] Bl[128] (10240B each).
static constexpr int STAGE_B  = 4 * 128 * 80;      // 40960 bytes
static constexpr int SMEM_TOT = 2 * STAGE_B + 512; // + slot array

template <int KSRC, int NDIM, bool G1>
__global__ void __launch_bounds__(128, 2)
moe_gemm_mma(const float* __restrict__ bias_all) {
    constexpr int NT  = NDIM / 128;
    constexpr int NKB = KSRC / 32;

    int cnts[Ee];
#pragma unroll
    for (int ee = 0; ee < Ee; ++ee) cnts[ee] = g_counts[ee];

    // block -> (expert, m-tile, n-tile)
    int b = blockIdx.x;
    int e = -1, mt = 0, nt = 0, acc0 = 0, ebase = 0, pre = 0;
    for (int ee = 0; ee < Ee; ++ee) {
        int mts = (cnts[ee] + 127) >> 7;
        int tot = mts * NT;
        if (b < acc0 + tot) { e = ee; ebase = pre; int loc = b - acc0; mt = loc / NT; nt = loc % NT; break; }
        acc0 += tot;
        pre  += cnts[ee];
    }
    if (e < 0) return;

    extern __shared__ char smem[];
    uint32_t smb = smem_u32(smem);
    int* s_slot = (int*)(smem + 2 * STAGE_B);
    int tid = threadIdx.x, wid = tid >> 5, lane = tid & 31;

    {
        int base = ebase + mt * 128, end = ebase + cnts[e];
        int r = base + tid;
        s_slot[tid] = (r < end) ? g_perm[r] : -1;
    }
    __syncthreads();

    const __nv_bfloat16* Wb =
        (G1 ? g_w1b : g_w2b) + ((size_t)e * NDIM + (size_t)nt * 128) * (2 * KSRC);

    // stage loader: 2048 16B chunks -> 16 per thread
    auto issue_stage = [&](int kb, int stg) {
        int k0 = kb * 32;
        uint32_t sb = smb + stg * STAGE_B;
#pragma unroll
        for (int i = 0; i < 16; ++i) {
            int q = i * 128 + tid;
            int tile = q >> 9;                // 0=Ah 1=Al 2=Bh 3=Bl
            int rem = q & 511;
            int r = rem >> 2, c = rem & 3;
            uint32_t dst = sb + tile * 10240 + r * 80 + c * 16;
            if (tile < 2) {
                int slot = s_slot[r];
                if (slot >= 0) {
                    const __nv_bfloat16* rowp =
                        G1 ? (g_xb + (size_t)(slot >> 1) * (2 * KSRC))
                           : (g_act + (size_t)slot * (2 * KSRC));
                    cp_async16(dst, rowp + tile * KSRC + k0 + c * 8, 16);
                } else {
                    cp_async16(dst, g_xb, 0); // zero-fill
                }
            } else {
                cp_async16(dst, Wb + (size_t)r * (2 * KSRC) + (tile & 1) * KSRC + k0 + c * 8, 16);
            }
        }
        CP_COMMIT();
    };

    int warp_m = wid >> 1, warp_n = wid & 1;  // 2 x 2 warp grid
    float accv[4][8][4];
#pragma unroll
    for (int mi = 0; mi < 4; ++mi)
#pragma unroll
        for (int ni = 0; ni < 8; ++ni)
#pragma unroll
            for (int j = 0; j < 4; ++j) accv[mi][ni][j] = 0.f;

    uint32_t lmrow = lane & 15;
    uint32_t lkc16 = (lane >> 4) * 16;

    issue_stage(0, 0);
    issue_stage(1, 1);

    for (int kb = 0; kb < NKB; ++kb) {
        CP_WAIT1();
        __syncthreads();
        uint32_t sb = smb + (kb & 1) * STAGE_B;
#pragma unroll
        for (int kk = 0; kk < 2; ++kk) {
            uint32_t ah[4][4], al[4][4], bh[8][2], bl[8][2];
            uint32_t aaddr = sb + (warp_m * 64 + lmrow) * 80 + kk * 32 + lkc16;
            uint32_t baddr = sb + 20480 + (warp_n * 64 + lmrow) * 80 + kk * 32 + lkc16;
#pragma unroll
            for (int mi = 0; mi < 4; ++mi) {
                LDSM4(ah[mi][0], ah[mi][1], ah[mi][2], ah[mi][3], aaddr + mi * 1280);
                LDSM4(al[mi][0], al[mi][1], al[mi][2], al[mi][3], aaddr + 10240 + mi * 1280);
            }
#pragma unroll
            for (int p = 0; p < 4; ++p)
                LDSM4(bh[2 * p][0], bh[2 * p + 1][0], bh[2 * p][1], bh[2 * p + 1][1],
                      baddr + p * 1280);
#pragma unroll
            for (int mi = 0; mi < 4; ++mi)
#pragma unroll
                for (int ni = 0; ni < 8; ++ni) {
                    MMA16816(accv[mi][ni], ah[mi], bh[ni][0], bh[ni][1]);
                    MMA16816(accv[mi][ni], al[mi], bh[ni][0], bh[ni][1]);
                }
#pragma unroll
            for (int p = 0; p < 4; ++p)
                LDSM4(bl[2 * p][0], bl[2 * p + 1][0], bl[2 * p][1], bl[2 * p + 1][1],
                      baddr + 10240 + p * 1280);
#pragma unroll
            for (int mi = 0; mi < 4; ++mi)
#pragma unroll
                for (int ni = 0; ni < 8; ++ni)
                    MMA16816(accv[mi][ni], ah[mi], bl[ni][0], bl[ni][1]);
        }
        __syncthreads();                         // readers done with other buf
        if (kb + 2 < NKB) issue_stage(kb + 2, kb & 1);
        else CP_COMMIT();                        // empty group keeps WAIT1 aligned
    }

    // ------------------------------------------------------------ epilogue
    int colb = nt * 128 + warp_n * 64 + 2 * (lane & 3);
    float2 bb[8];
#pragma unroll
    for (int ni = 0; ni < 8; ++ni) {
        bb[ni].x = bias_all[(size_t)e * NDIM + colb + ni * 8];
        bb[ni].y = bias_all[(size_t)e * NDIM + colb + ni * 8 + 1];
    }
#pragma unroll
    for (int mi = 0; mi < 4; ++mi) {
#pragma unroll
        for (int h = 0; h < 2; ++h) {
            int row = warp_m * 64 + mi * 16 + (lane >> 2) + h * 8;
            int slot = s_slot[row];
            if (slot < 0) continue;
            if (G1) {
                __nv_bfloat16* rowp = g_act + (size_t)slot * (2 * Ff);
#pragma unroll
                for (int ni = 0; ni < 8; ++ni) {
                    int n = colb + ni * 8;
                    float v0 = accv[mi][ni][2 * h + 0] + bb[ni].x;
                    float v1 = accv[mi][ni][2 * h + 1] + bb[ni].y;
                    v0 = 0.5f * v0 * (1.f + erff(v0 * 0.70710678118654752f));
                    v1 = 0.5f * v1 * (1.f + erff(v1 * 0.70710678118654752f));
                    __nv_bfloat16 h0 = __float2bfloat16_rn(v0);
                    __nv_bfloat16 h1 = __float2bfloat16_rn(v1);
                    __nv_bfloat16 l0 = __float2bfloat16_rn(v0 - __bfloat162float(h0));
                    __nv_bfloat16 l1 = __float2bfloat16_rn(v1 - __bfloat162float(h1));
                    __nv_bfloat16 hp[2] = {h0, h1};
                    __nv_bfloat16 lp[2] = {l0, l1};
                    *(uint32_t*)(rowp + n)      = *(uint32_t*)hp;
                    *(uint32_t*)(rowp + Ff + n) = *(uint32_t*)lp;
                }
            } else {
                float* rowp = g_y + (size_t)slot * Hh;
#pragma unroll
                for (int ni = 0; ni < 8; ++ni) {
                    int n = colb + ni * 8;
                    float2 v;
                    v.x = accv[mi][ni][2 * h + 0] + bb[ni].x;
                    v.y = accv[mi][ni][2 * h + 1] + bb[ni].y;
                    *(float2*)(rowp + n) = v;
                }
            }
        }
    }
}

// ---------------------------------------------------------------- combine
__global__ void combine_kernel(float* __restrict__ out) {
    int t = blockIdx.x;
    float p0 = g_topk_p[2 * t], p1 = g_topk_p[2 * t + 1];
    const float4* y0 = (const float4*)(g_y + (size_t)(2 * t) * Hh);
    const float4* y1 = (const float4*)(g_y + (size_t)(2 * t + 1) * Hh);
    float4* o = (float4*)(out + (size_t)t * Hh);
    int i = threadIdx.x;
    float4 a = y0[i], b = y1[i];
    o[i] = make_float4(p0 * a.x + p1 * b.x, p0 * a.y + p1 * b.y,
                       p0 * a.z + p1 * b.z, p0 * a.w + p1 * b.w);
}

// ---------------------------------------------------------------- launch
extern "C" void kernel_launch(void* const* d_in, const int* in_sizes, int n_in,
                              void* d_out, int out_size) {
    (void)in_sizes; (void)n_in; (void)out_size;
    const float* x    = (const float*)d_in[0];
    const float* rw   = (const float*)d_in[1];
    const float* fc1w = (const float*)d_in[2];
    const float* fc1b = (const float*)d_in[3];
    const float* fc2w = (const float*)d_in[4];
    const float* fc2b = (const float*)d_in[5];

    float* out       = (float*)d_out;                 // [T, Hh]
    float* out_probs = out + (size_t)T * Hh;          // [T, Ee]
    float* out_idx   = out_probs + (size_t)T * Ee;    // [T, 2] as float

    cudaFuncSetAttribute(moe_gemm_mma<Hh, Ff, true>,
                         cudaFuncAttributeMaxDynamicSharedMemorySize, SMEM_TOT);
    cudaFuncSetAttribute(moe_gemm_mma<Ff, Hh, false>,
                         cudaFuncAttributeMaxDynamicSharedMemorySize, SMEM_TOT);

    // 1: conversions + counter zeroing (fused)
    fused_prep<<<(N4_TOT + 255) / 256, 256>>>(x, fc1w, fc2w);
    // 2: router
    router_kernel<<<T / 8, 256>>>(x, rw, out_probs, out_idx);
    // 3: scatter (inline scan)
    scatter_kernel<<<T / 256, 256>>>();
    // 4: GEMM1 — the ncu-profiled launch
    moe_gemm_mma<Hh, Ff, true ><<<136 * (Ff / 128), 128, SMEM_TOT>>>(fc1b);
    // 5: GEMM2
    moe_gemm_mma<Ff, Hh, false><<<136 * (Hh / 128), 128, SMEM_TOT>>>(fc2b);
    // 6: combine
    combine_kernel<<<T, 128>>>(out);
}